// round 11
// baseline (speedup 1.0000x reference)
#include <cuda_runtime.h>
#include <math.h>
#include <stdint.h>

// Problem constants
#define Bp 4
#define Np 2048
#define Cp 512
#define Hp 8
#define Dp 64
#define Wp 4
#define NWp 512
#define KEEP 64

// Scratch (device globals; no allocation allowed)
__device__ float g_q[Bp*Np*Hp*Dp];       // [B,N,H,D]
__device__ float g_k[Bp*Np*Hp*Dp];
__device__ float g_v[Bp*Np*Hp*Dp];
__device__ float g_attn[Bp*Np*Hp*Dp];    // [B,N,H*D] (tf32-rounded values)
__device__ int   g_idx[Bp*Hp*NWp*KEEP];  // [B,H,NW,64]
__device__ float g_Wperm[Cp*3*Hp*Dp];    // Wqkv permuted to (s,h,d), tf32-rounded
__device__ float g_bperm[3*Hp*Dp];
__device__ float g_x32[Bp*Np*Cp];        // x, tf32-rounded
__device__ float g_Wo32[Cp*Cp];          // Wo, tf32-rounded

// ---------------------------------------------------------------------------
// tf32 / async-copy helpers
// ---------------------------------------------------------------------------
__device__ __forceinline__ float to_tf32(float x) {
    unsigned u;
    asm("cvt.rna.tf32.f32 %0, %1;" : "=r"(u) : "f"(x));
    return __uint_as_float(u);
}

__device__ __forceinline__ void mma_tf32(float4& d,
    unsigned a0, unsigned a1, unsigned a2, unsigned a3,
    unsigned b0, unsigned b1)
{
    asm volatile(
        "mma.sync.aligned.m16n8k8.row.col.f32.tf32.tf32.f32 "
        "{%0,%1,%2,%3}, {%4,%5,%6,%7}, {%8,%9}, {%0,%1,%2,%3};\n"
        : "+f"(d.x), "+f"(d.y), "+f"(d.z), "+f"(d.w)
        : "r"(a0), "r"(a1), "r"(a2), "r"(a3), "r"(b0), "r"(b1));
}

__device__ __forceinline__ void cp16(float* dst_smem, const float* src) {
    unsigned d = (unsigned)__cvta_generic_to_shared(dst_smem);
    asm volatile("cp.async.cg.shared.global [%0], [%1], 16;" :: "r"(d), "l"(src));
}
#define CP_COMMIT() asm volatile("cp.async.commit_group;")
#define CP_WAIT0()  asm volatile("cp.async.wait_group 0;")

// ---------------------------------------------------------------------------
// Producers: tf32-convert x / Wo; permute+convert Wqkv.
// ---------------------------------------------------------------------------
__global__ __launch_bounds__(256) void convX_kernel(const float* __restrict__ x)
{
    int i = blockIdx.x*256 + threadIdx.x;
    float4 v = *(const float4*)(x + (size_t)i*4);
    v.x = to_tf32(v.x); v.y = to_tf32(v.y); v.z = to_tf32(v.z); v.w = to_tf32(v.w);
    *(float4*)(g_x32 + (size_t)i*4) = v;
}

__global__ __launch_bounds__(256) void convWo_kernel(const float* __restrict__ Wo)
{
    int i = blockIdx.x*256 + threadIdx.x;
    float4 v = *(const float4*)(Wo + (size_t)i*4);
    v.x = to_tf32(v.x); v.y = to_tf32(v.y); v.z = to_tf32(v.z); v.w = to_tf32(v.w);
    *(float4*)(g_Wo32 + (size_t)i*4) = v;
}

__global__ __launch_bounds__(256) void permW_kernel(
    const float* __restrict__ Wqkv, const float* __restrict__ bqkv)
{
    int idx = blockIdx.x*256 + threadIdx.x;      // 0 .. 512*1536-1
    int u = idx % 1536;
    int k = idx / 1536;
    int s = u >> 9, hd = u & 511;
    g_Wperm[idx] = to_tf32(Wqkv[(size_t)k*1536 + hd*3 + s]);
    if (idx < 1536) g_bperm[idx] = bqkv[(idx & 511)*3 + (idx >> 9)];
}

// ---------------------------------------------------------------------------
// tf32 GEMM, cp.async double-buffered. Operands already tf32-rounded.
// byOff: chunking along M (batch) in units of 128-row tiles.
// ---------------------------------------------------------------------------
#define AS_STRIDE 36
#define BS_STRIDE 132
#define AS_STAGE (128*AS_STRIDE)
#define BS_STAGE (32*BS_STRIDE)
#define GEMM_SMEM ((2*AS_STAGE + 2*BS_STAGE)*4)  // 70656 bytes

template<int EPI>
__global__ __launch_bounds__(256, 2) void gemm_tf32_kernel(
    const float* __restrict__ biasIn,
    float* __restrict__ Cout,
    int Nn, int byOff)
{
    extern __shared__ float smem[];
    float* AsB = smem;
    float* BsB = smem + 2*AS_STAGE;

    const int Kk = 512;
    const float* A    = (EPI == 0) ? (const float*)g_x32   : (const float*)g_attn;
    const float* Bw   = (EPI == 0) ? (const float*)g_Wperm : (const float*)g_Wo32;
    const float* bias = (EPI == 0) ? (const float*)g_bperm : biasIn;

    int tid = threadIdx.x;
    int bx = blockIdx.x, by = blockIdx.y + byOff;
    int warp = tid >> 5, lane = tid & 31;
    int wm = warp & 1, wn = warp >> 1;
    int gid = lane >> 2, tig = lane & 3;

    float4 acc[4][4];
    #pragma unroll
    for (int i = 0; i < 4; i++)
        #pragma unroll
        for (int j = 0; j < 4; j++) acc[i][j] = make_float4(0.f,0.f,0.f,0.f);

    auto load_tile = [&](int st, int kt) {
        int k0 = kt*32;
        float* As = AsB + st*AS_STAGE;
        float* Bs = BsB + st*BS_STAGE;
        #pragma unroll
        for (int i = 0; i < 4; i++) {
            int f = tid + i*256;
            cp16(&As[(f>>3)*AS_STRIDE + (f&7)*4],
                 A + (size_t)(by*128 + (f>>3))*Kk + k0 + (f&7)*4);
            cp16(&Bs[(f>>5)*BS_STRIDE + (f&31)*4],
                 Bw + (size_t)(k0 + (f>>5))*Nn + bx*128 + (f&31)*4);
        }
        CP_COMMIT();
    };

    load_tile(0, 0);
    CP_WAIT0();
    __syncthreads();

    int s = 0;
    for (int kt = 0; kt < 16; kt++) {
        if (kt < 15) load_tile(s^1, kt+1);

        const float* Asc = AsB + s*AS_STAGE;
        const float* Bsc = BsB + s*BS_STAGE;
        #pragma unroll
        for (int ks = 0; ks < 4; ks++) {
            int k0 = ks*8;
            unsigned af[4][4], bf[4][2];
            #pragma unroll
            for (int i = 0; i < 4; i++) {
                int r = wm*64 + i*16 + gid;
                af[i][0] = __float_as_uint(Asc[ r    *AS_STRIDE + k0 + tig]);
                af[i][1] = __float_as_uint(Asc[(r+8)*AS_STRIDE + k0 + tig]);
                af[i][2] = __float_as_uint(Asc[ r    *AS_STRIDE + k0 + tig + 4]);
                af[i][3] = __float_as_uint(Asc[(r+8)*AS_STRIDE + k0 + tig + 4]);
            }
            #pragma unroll
            for (int j = 0; j < 4; j++) {
                int c = wn*32 + j*8 + gid;
                bf[j][0] = __float_as_uint(Bsc[(k0 + tig    )*BS_STRIDE + c]);
                bf[j][1] = __float_as_uint(Bsc[(k0 + tig + 4)*BS_STRIDE + c]);
            }
            #pragma unroll
            for (int i = 0; i < 4; i++)
                #pragma unroll
                for (int j = 0; j < 4; j++)
                    mma_tf32(acc[i][j], af[i][0], af[i][1], af[i][2], af[i][3],
                             bf[j][0], bf[j][1]);
        }

        if (kt < 15) CP_WAIT0();
        __syncthreads();
        s ^= 1;
    }

    float* dst;
    int colBase, rowStride;
    if (EPI == 0) {
        int sq = bx >> 2;
        dst = (sq == 0) ? g_q : (sq == 1) ? g_k : g_v;
        colBase = (bx & 3)*128;
        rowStride = 512;
    } else {
        dst = Cout;
        colBase = bx*128;
        rowStride = Nn;
    }
    #pragma unroll
    for (int i = 0; i < 4; i++) {
        int m0 = by*128 + wm*64 + i*16 + gid;
        #pragma unroll
        for (int j = 0; j < 4; j++) {
            int cl = wn*32 + j*8 + tig*2;
            float bz0 = bias[bx*128 + cl];
            float bz1 = bias[bx*128 + cl + 1];
            float4 d = acc[i][j];
            float2 o0 = make_float2(d.x + bz0, d.y + bz1);
            float2 o1 = make_float2(d.z + bz0, d.w + bz1);
            *(float2*)(dst + (size_t)m0*rowStride + colBase + cl)     = o0;
            *(float2*)(dst + (size_t)(m0+8)*rowStride + colBase + cl) = o1;
        }
    }
}

// ---------------------------------------------------------------------------
// Block-wide inclusive scan (256 threads) via warp shuffles.
// ---------------------------------------------------------------------------
__device__ __forceinline__ unsigned blockScanIncl(unsigned v, unsigned* warpSums, int t)
{
    int lane = t & 31, wid = t >> 5;
    #pragma unroll
    for (int off = 1; off < 32; off <<= 1) {
        unsigned n = __shfl_up_sync(0xffffffffu, v, off);
        if (lane >= off) v += n;
    }
    if (lane == 31) warpSums[wid] = v;
    __syncthreads();
    if (wid == 0) {
        unsigned s = (lane < 8) ? warpSums[lane] : 0u;
        #pragma unroll
        for (int off = 1; off < 8; off <<= 1) {
            unsigned n = __shfl_up_sync(0xffffffffu, s, off);
            if (lane >= off) s += n;
        }
        if (lane < 8) warpSums[lane] = s;
    }
    __syncthreads();
    if (wid > 0) v += warpSums[wid - 1];
    return v;
}

template<int NB>
__device__ __forceinline__ void findThresholdBin(
    const unsigned* hist, unsigned r, unsigned* warpSums, unsigned* sOut, int t)
{
    const int PER = NB / 256;
    unsigned loc[PER];
    unsigned s = 0;
    #pragma unroll
    for (int i = 0; i < PER; i++) { loc[i] = hist[t*PER + i]; s += loc[i]; }
    unsigned incl = blockScanIncl(s, warpSums, t);
    unsigned excl = incl - s;
    if (excl < r && r <= incl) {
        unsigned cum = excl;
        #pragma unroll
        for (int i = 0; i < PER; i++) {
            if (cum + loc[i] >= r) { sOut[0] = t*PER + i; sOut[1] = cum; break; }
            cum += loc[i];
        }
    }
    __syncthreads();
}

// ---------------------------------------------------------------------------
// Selection: pass-1 11-bit radix + exact rank-count on candidates.
// pOff chunks the (b,h,nw) space.
// ---------------------------------------------------------------------------
__global__ __launch_bounds__(256) void select_kernel(
    const float* __restrict__ pareto,        // [B,H,NW,N]
    const unsigned char* __restrict__ mask,  // [B,N] bool
    int pOff)
{
    __shared__ unsigned hist[2048];
    __shared__ unsigned cand[2048];
    __shared__ unsigned warpSums[8];
    __shared__ unsigned sOut[2];
    __shared__ unsigned sCnt;
    __shared__ unsigned sT, sRR;

    int p = blockIdx.x + pOff;
    int nw = p & (NWp-1);
    int b  = p / (Hp*NWp);
    int t  = threadIdx.x;

    const float* prow = pareto + (size_t)p * Np;
    const unsigned char* mrow = mask + (size_t)b * Np;

    unsigned long long mbits = *(const unsigned long long*)(mrow + t*8);
    unsigned key[8];
    #pragma unroll
    for (int v = 0; v < 2; v++) {
        float4 nz = *(const float4*)(prow + t*8 + v*4);
        float noise[4] = {nz.x, nz.y, nz.z, nz.w};
        int ag = nw - (t*2 + v); if (ag < 0) ag = -ag;
        float gridv = (float)ag;
        #pragma unroll
        for (int i = 0; i < 4; i++) {
            float val = gridv - noise[i];
            if ((mbits >> ((v*4 + i)*8)) & 0xFFull) val = 3.402823466e38f;
            unsigned ub = __float_as_uint(val);
            ub ^= ((unsigned)((int)ub >> 31)) | 0x80000000u;
            key[v*4 + i] = ub;
        }
    }

    #pragma unroll
    for (int i = 0; i < 8; i++) hist[t*8 + i] = 0;
    __syncthreads();
    #pragma unroll
    for (int i = 0; i < 8; i++)
        atomicAdd(&hist[key[i] >> 21], 1u);
    __syncthreads();

    unsigned r = 64;
    findThresholdBin<2048>(hist, r, warpSums, sOut, t);
    unsigned bin1 = sOut[0];
    r -= sOut[1];
    __syncthreads();

    if (t == 0) sCnt = 0;
    __syncthreads();
    #pragma unroll
    for (int i = 0; i < 8; i++)
        if ((key[i] >> 21) == bin1)
            cand[atomicAdd(&sCnt, 1u)] = key[i];
    __syncthreads();
    unsigned E = sCnt;

    if (E > 256) {
        #pragma unroll
        for (int i = 0; i < 8; i++) hist[t*8 + i] = 0;
        unsigned kk[8]; int n = 0;
        for (unsigned j = t; j < E; j += 256) kk[n++] = cand[j];
        __syncthreads();
        for (int i = 0; i < n; i++)
            atomicAdd(&hist[(kk[i] >> 10) & 0x7FFu], 1u);
        __syncthreads();
        findThresholdBin<2048>(hist, r, warpSums, sOut, t);
        unsigned bin2 = sOut[0];
        r -= sOut[1];
        __syncthreads();
        if (t == 0) sCnt = 0;
        __syncthreads();
        for (int i = 0; i < n; i++)
            if (((kk[i] >> 10) & 0x7FFu) == bin2)
                cand[atomicAdd(&sCnt, 1u)] = kk[i];
        __syncthreads();
        E = sCnt;
    }

    for (unsigned e = t; e < E; e += 256) {
        unsigned ke = cand[e];
        unsigned less = 0, eq = 0;
        for (unsigned i = 0; i < E; i++) {
            unsigned ki = cand[i];
            less += (ki < ke);
            eq   += (ki == ke);
        }
        if (less < r && r <= less + eq) { sT = ke; sRR = r - less; }
    }
    __syncthreads();
    unsigned T = sT;
    unsigned rr = sRR;

    unsigned lessC = 0, eqC = 0;
    #pragma unroll
    for (int i = 0; i < 8; i++) {
        lessC += (key[i] < T);
        eqC   += (key[i] == T);
    }
    unsigned packed = lessC | (eqC << 16);
    unsigned incl = blockScanIncl(packed, warpSums, t);
    unsigned lb = (incl & 0xFFFFu) - lessC;
    unsigned eb = (incl >> 16)     - eqC;

    int* oidx = g_idx + (size_t)p * KEEP;
    #pragma unroll
    for (int i = 0; i < 8; i++) {
        int j = t*8 + i;
        unsigned k = key[i];
        if (k < T) {
            oidx[lb + min(eb, rr)] = j;
            lb++;
        } else if (k == T) {
            if (eb < rr) oidx[lb + eb] = j;
            eb++;
        }
    }
}

// ---------------------------------------------------------------------------
// Attention: one block per (b,h,nw); 256 threads. pOff chunks by batch.
// ---------------------------------------------------------------------------
#define PADR 68
__global__ __launch_bounds__(256) void attn_kernel(
    const float* __restrict__ pos_bias,      // [H,N,N]
    const unsigned char* __restrict__ mask,  // [B,N]
    int pOff)
{
    __shared__ int   sidx[KEEP];
    __shared__ float qs[Wp][PADR];
    __shared__ float sd[Wp][PADR];
    __shared__ float pb_s[Wp][PADR];
    __shared__ unsigned char km_s[KEEP];
    __shared__ float partial[4][Wp][Dp];

    int p  = blockIdx.x + pOff;
    int nw = p & (NWp-1);
    int bh = p >> 9;
    int h  = bh & (Hp-1);
    int b  = bh >> 3;
    int t  = threadIdx.x;

    if (t < KEEP) sidx[t] = g_idx[(size_t)p * KEEP + t];
    {
        int w = t >> 6, d = t & 63;
        qs[w][d] = g_q[((size_t)(b*Np + nw*Wp + w)*Hp + h)*Dp + d];
    }
    __syncthreads();

    {
        int w = t >> 6, z = t & 63;
        int key = sidx[z];
        pb_s[w][z] = __ldg(pos_bias + ((size_t)h*Np + nw*Wp + w)*Np + key);
        if (t < KEEP) km_s[t] = mask[(size_t)b*Np + sidx[t]];
    }
    __syncthreads();

    const float scale = 0.125f;
    {
        int z = t >> 2, quar = t & 3;
        int row = sidx[z];
        const float* kp = g_k + ((size_t)(b*Np + row)*Hp + h)*Dp + quar*16;
        float4 kv[4];
        #pragma unroll
        for (int i = 0; i < 4; i++) kv[i] = __ldg((const float4*)(kp + i*4));

        bool qm = mask[(size_t)b*Np + nw*Wp + quar] != 0;

        float pw[4] = {0.f, 0.f, 0.f, 0.f};
        #pragma unroll
        for (int i = 0; i < 4; i++) {
            #pragma unroll
            for (int w = 0; w < 4; w++) {
                float4 qv = *(const float4*)&qs[w][quar*16 + i*4];
                pw[w] += qv.x*kv[i].x + qv.y*kv[i].y + qv.z*kv[i].z + qv.w*kv[i].w;
            }
        }
        #pragma unroll
        for (int w = 0; w < 4; w++) {
            pw[w] += __shfl_xor_sync(0xffffffffu, pw[w], 1);
            pw[w] += __shfl_xor_sync(0xffffffffu, pw[w], 2);
        }
        float val = pw[quar]*scale + pb_s[quar][z];
        if (qm && km_s[z]) val = -3.402823466e38f;
        sd[quar][z] = val;
    }
    __syncthreads();

    if (t < 128) {
        int w = t >> 5, lane = t & 31;
        float v0 = sd[w][lane], v1 = sd[w][lane+32];
        float m = fmaxf(v0, v1);
        #pragma unroll
        for (int off = 16; off > 0; off >>= 1)
            m = fmaxf(m, __shfl_xor_sync(0xffffffffu, m, off));
        float e0 = __expf(v0 - m), e1 = __expf(v1 - m);
        float s = e0 + e1;
        #pragma unroll
        for (int off = 16; off > 0; off >>= 1)
            s += __shfl_xor_sync(0xffffffffu, s, off);
        float inv = 1.f / s;
        sd[w][lane]    = e0*inv;
        sd[w][lane+32] = e1*inv;
    }
    __syncthreads();

    {
        int g = t >> 6, d = t & 63;
        const float* vbase = g_v + ((size_t)b*Np*Hp + h)*Dp + d;
        float a0 = 0.f, a1 = 0.f, a2 = 0.f, a3 = 0.f;
        #pragma unroll
        for (int c = 0; c < 4; c++) {
            float4 s0 = *(const float4*)&sd[0][g*16 + c*4];
            float4 s1 = *(const float4*)&sd[1][g*16 + c*4];
            float4 s2 = *(const float4*)&sd[2][g*16 + c*4];
            float4 s3 = *(const float4*)&sd[3][g*16 + c*4];
            float sv0[4] = {s0.x, s0.y, s0.z, s0.w};
            float sv1[4] = {s1.x, s1.y, s1.z, s1.w};
            float sv2[4] = {s2.x, s2.y, s2.z, s2.w};
            float sv3[4] = {s3.x, s3.y, s3.z, s3.w};
            #pragma unroll
            for (int j = 0; j < 4; j++) {
                int z = g*16 + c*4 + j;
                int row = sidx[z];
                float vv = __ldg(vbase + (size_t)row*Hp*Dp);
                a0 += sv0[j] * vv;
                a1 += sv1[j] * vv;
                a2 += sv2[j] * vv;
                a3 += sv3[j] * vv;
            }
        }
        partial[g][0][d] = a0;
        partial[g][1][d] = a1;
        partial[g][2][d] = a2;
        partial[g][3][d] = a3;
    }
    __syncthreads();

    {
        int w = t >> 6, d = t & 63;
        float acc = partial[0][w][d] + partial[1][w][d]
                  + partial[2][w][d] + partial[3][w][d];
        g_attn[((size_t)b*Np + nw*Wp + w)*(Hp*Dp) + h*Dp + d] = to_tf32(acc);
    }
}

// ---------------------------------------------------------------------------
extern "C" void kernel_launch(void* const* d_in, const int* in_sizes, int n_in,
                              void* d_out, int out_size)
{
    const float* x            = (const float*)d_in[0];
    const unsigned char* mask = (const unsigned char*)d_in[1];
    const float* pos_bias     = (const float*)d_in[2];
    const float* pareto       = (const float*)d_in[3];
    const float* Wqkv         = (const float*)d_in[4];
    const float* bqkv         = (const float*)d_in[5];
    const float* Wo           = (const float*)d_in[6];
    const float* bo           = (const float*)d_in[7];
    float* out                = (float*)d_out;

    (void)in_sizes; (void)n_in; (void)out_size;

    static cudaStream_t s2 = nullptr, s3 = nullptr;
    static cudaEvent_t evFork = nullptr, evPerm = nullptr, evWo = nullptr;
    static cudaEvent_t evG0[Bp], evSel[Bp], evA[Bp], evTail;
    if (s2 == nullptr) {
        cudaStreamCreateWithFlags(&s2, cudaStreamNonBlocking);
        cudaStreamCreateWithFlags(&s3, cudaStreamNonBlocking);
        cudaEventCreateWithFlags(&evFork, cudaEventDisableTiming);
        cudaEventCreateWithFlags(&evPerm, cudaEventDisableTiming);
        cudaEventCreateWithFlags(&evWo, cudaEventDisableTiming);
        cudaEventCreateWithFlags(&evTail, cudaEventDisableTiming);
        for (int b = 0; b < Bp; b++) {
            cudaEventCreateWithFlags(&evG0[b], cudaEventDisableTiming);
            cudaEventCreateWithFlags(&evSel[b], cudaEventDisableTiming);
            cudaEventCreateWithFlags(&evA[b], cudaEventDisableTiming);
        }
        cudaFuncSetAttribute(gemm_tf32_kernel<0>,
            cudaFuncAttributeMaxDynamicSharedMemorySize, GEMM_SMEM);
        cudaFuncSetAttribute(gemm_tf32_kernel<1>,
            cudaFuncAttributeMaxDynamicSharedMemorySize, GEMM_SMEM);
    }

    // Side stream: producers, then select in 4 batch chunks, then Wo convert.
    cudaEventRecord(evFork, 0);
    cudaStreamWaitEvent(s2, evFork, 0);
    permW_kernel<<<(Cp*3*Hp*Dp)/256, 256, 0, s2>>>(Wqkv, bqkv);
    convX_kernel<<<(Bp*Np*Cp/4)/256, 256, 0, s2>>>(x);
    cudaEventRecord(evPerm, s2);
    for (int b = 0; b < Bp; b++) {
        select_kernel<<<Hp*NWp, 256, 0, s2>>>(pareto, mask, b*Hp*NWp);
        cudaEventRecord(evSel[b], s2);
    }
    convWo_kernel<<<(Cp*Cp/4)/256, 256, 0, s2>>>(Wo);
    cudaEventRecord(evWo, s2);

    // Main stream: QKV GEMM in 4 batch chunks (16 row-tiles each).
    cudaStreamWaitEvent(0, evPerm, 0);
    for (int b = 0; b < Bp; b++) {
        dim3 grid(3*Hp*Dp/128, Np/128);   // 12 x 16
        gemm_tf32_kernel<0><<<grid, 256, GEMM_SMEM>>>(nullptr, nullptr, 3*Hp*Dp, b*(Np/128));
        cudaEventRecord(evG0[b], 0);
    }

    // Stream s3: attention chunks, each gated on its batch's qkv + select.
    for (int b = 0; b < Bp; b++) {
        cudaStreamWaitEvent(s3, evG0[b], 0);
        cudaStreamWaitEvent(s3, evSel[b], 0);
        attn_kernel<<<Hp*NWp, 256, 0, s3>>>(pos_bias, mask, b*Hp*NWp);
        cudaEventRecord(evA[b], s3);
    }

    // Main stream: output projection chunks, each gated on its attn chunk.
    cudaStreamWaitEvent(0, evWo, 0);
    for (int b = 0; b < Bp; b++) {
        cudaStreamWaitEvent(0, evA[b], 0);
        dim3 grid(Cp/128, Np/128);        // 4 x 16
        gemm_tf32_kernel<1><<<grid, 256, GEMM_SMEM>>>(bo, out, Cp, b*(Np/128));
    }
}

// round 12
// speedup vs baseline: 1.0944x; 1.0944x over previous
#include <cuda_runtime.h>
#include <math.h>
#include <stdint.h>

// Problem constants
#define Bp 4
#define Np 2048
#define Cp 512
#define Hp 8
#define Dp 64
#define Wp 4
#define NWp 512
#define KEEP 64

// Scratch (device globals; no allocation allowed)
__device__ float g_q[Bp*Np*Hp*Dp];       // [B,N,H,D]
__device__ float g_k[Bp*Np*Hp*Dp];
__device__ float g_v[Bp*Np*Hp*Dp];
__device__ float g_attn[Bp*Np*Hp*Dp];    // [B,N,H*D] (tf32-rounded values)
__device__ int   g_idx[Bp*Hp*NWp*KEEP];  // [B,H,NW,64]
__device__ float g_Wperm[Cp*3*Hp*Dp];    // Wqkv permuted to (s,h,d), tf32-rounded
__device__ float g_bperm[3*Hp*Dp];
__device__ float g_x32[Bp*Np*Cp];        // x, tf32-rounded
__device__ float g_Wo32[Cp*Cp];          // Wo, tf32-rounded

// ---------------------------------------------------------------------------
// tf32 / async-copy helpers
// ---------------------------------------------------------------------------
__device__ __forceinline__ float to_tf32(float x) {
    unsigned u;
    asm("cvt.rna.tf32.f32 %0, %1;" : "=r"(u) : "f"(x));
    return __uint_as_float(u);
}

__device__ __forceinline__ void mma_tf32(float4& d,
    unsigned a0, unsigned a1, unsigned a2, unsigned a3,
    unsigned b0, unsigned b1)
{
    asm volatile(
        "mma.sync.aligned.m16n8k8.row.col.f32.tf32.tf32.f32 "
        "{%0,%1,%2,%3}, {%4,%5,%6,%7}, {%8,%9}, {%0,%1,%2,%3};\n"
        : "+f"(d.x), "+f"(d.y), "+f"(d.z), "+f"(d.w)
        : "r"(a0), "r"(a1), "r"(a2), "r"(a3), "r"(b0), "r"(b1));
}

__device__ __forceinline__ void cp16(float* dst_smem, const float* src) {
    unsigned d = (unsigned)__cvta_generic_to_shared(dst_smem);
    asm volatile("cp.async.cg.shared.global [%0], [%1], 16;" :: "r"(d), "l"(src));
}
#define CP_COMMIT() asm volatile("cp.async.commit_group;")
#define CP_WAIT0()  asm volatile("cp.async.wait_group 0;")
#define CP_WAIT1()  asm volatile("cp.async.wait_group 1;")

// ---------------------------------------------------------------------------
// Producers: tf32-convert x / Wo; permute+convert Wqkv.
// ---------------------------------------------------------------------------
__global__ __launch_bounds__(256) void convX_kernel(const float* __restrict__ x)
{
    int i = blockIdx.x*256 + threadIdx.x;
    float4 v = *(const float4*)(x + (size_t)i*4);
    v.x = to_tf32(v.x); v.y = to_tf32(v.y); v.z = to_tf32(v.z); v.w = to_tf32(v.w);
    *(float4*)(g_x32 + (size_t)i*4) = v;
}

__global__ __launch_bounds__(256) void convWo_kernel(const float* __restrict__ Wo)
{
    int i = blockIdx.x*256 + threadIdx.x;
    float4 v = *(const float4*)(Wo + (size_t)i*4);
    v.x = to_tf32(v.x); v.y = to_tf32(v.y); v.z = to_tf32(v.z); v.w = to_tf32(v.w);
    *(float4*)(g_Wo32 + (size_t)i*4) = v;
}

__global__ __launch_bounds__(256) void permW_kernel(
    const float* __restrict__ Wqkv, const float* __restrict__ bqkv)
{
    int idx = blockIdx.x*256 + threadIdx.x;      // 0 .. 512*1536-1
    int u = idx % 1536;
    int k = idx / 1536;
    int s = u >> 9, hd = u & 511;
    g_Wperm[idx] = to_tf32(Wqkv[(size_t)k*1536 + hd*3 + s]);
    if (idx < 1536) g_bperm[idx] = bqkv[(idx & 511)*3 + (idx >> 9)];
}

// ---------------------------------------------------------------------------
// tf32 GEMM, cp.async 3-stage pipeline. Operands already tf32-rounded.
// ---------------------------------------------------------------------------
#define AS_STRIDE 36
#define BS_STRIDE 132
#define AS_STAGE (128*AS_STRIDE)
#define BS_STAGE (32*BS_STRIDE)
#define STAGE_FLOATS (AS_STAGE + BS_STAGE)
#define GEMM_SMEM (3*STAGE_FLOATS*4)   // 105984 bytes

template<int EPI>
__global__ __launch_bounds__(256, 2) void gemm_tf32_kernel(
    const float* __restrict__ biasIn,
    float* __restrict__ Cout,
    int Nn)
{
    extern __shared__ float smem[];
    // stage layout: [stage][ A(128x36) | B(32x132) ]
    const int Kk = 512;
    const float* A    = (EPI == 0) ? (const float*)g_x32   : (const float*)g_attn;
    const float* Bw   = (EPI == 0) ? (const float*)g_Wperm : (const float*)g_Wo32;
    const float* bias = (EPI == 0) ? (const float*)g_bperm : biasIn;

    int tid = threadIdx.x;
    int bx = blockIdx.x, by = blockIdx.y;
    int warp = tid >> 5, lane = tid & 31;
    int wm = warp & 1, wn = warp >> 1;
    int gid = lane >> 2, tig = lane & 3;

    float4 acc[4][4];
    #pragma unroll
    for (int i = 0; i < 4; i++)
        #pragma unroll
        for (int j = 0; j < 4; j++) acc[i][j] = make_float4(0.f,0.f,0.f,0.f);

    auto load_tile = [&](int st, int kt) {
        int k0 = kt*32;
        float* As = smem + st*STAGE_FLOATS;
        float* Bs = As + AS_STAGE;
        #pragma unroll
        for (int i = 0; i < 4; i++) {
            int f = tid + i*256;
            cp16(&As[(f>>3)*AS_STRIDE + (f&7)*4],
                 A + (size_t)(by*128 + (f>>3))*Kk + k0 + (f&7)*4);
            cp16(&Bs[(f>>5)*BS_STRIDE + (f&31)*4],
                 Bw + (size_t)(k0 + (f>>5))*Nn + bx*128 + (f&31)*4);
        }
        CP_COMMIT();
    };

    load_tile(0, 0);
    load_tile(1, 1);
    CP_WAIT1();            // tile 0 arrived
    __syncthreads();

    for (int kt = 0; kt < 16; kt++) {
        int st = kt % 3;

        // issue load for kt+2 into the free stage (overlaps this compute)
        if (kt + 2 < 16) load_tile((kt + 2) % 3, kt + 2);

        const float* Asc = smem + st*STAGE_FLOATS;
        const float* Bsc = Asc + AS_STAGE;
        #pragma unroll
        for (int ks = 0; ks < 4; ks++) {
            int k0 = ks*8;
            unsigned af[4][4], bf[4][2];
            #pragma unroll
            for (int i = 0; i < 4; i++) {
                int r = wm*64 + i*16 + gid;
                af[i][0] = __float_as_uint(Asc[ r    *AS_STRIDE + k0 + tig]);
                af[i][1] = __float_as_uint(Asc[(r+8)*AS_STRIDE + k0 + tig]);
                af[i][2] = __float_as_uint(Asc[ r    *AS_STRIDE + k0 + tig + 4]);
                af[i][3] = __float_as_uint(Asc[(r+8)*AS_STRIDE + k0 + tig + 4]);
            }
            #pragma unroll
            for (int j = 0; j < 4; j++) {
                int c = wn*32 + j*8 + gid;
                bf[j][0] = __float_as_uint(Bsc[(k0 + tig    )*BS_STRIDE + c]);
                bf[j][1] = __float_as_uint(Bsc[(k0 + tig + 4)*BS_STRIDE + c]);
            }
            #pragma unroll
            for (int i = 0; i < 4; i++)
                #pragma unroll
                for (int j = 0; j < 4; j++)
                    mma_tf32(acc[i][j], af[i][0], af[i][1], af[i][2], af[i][3],
                             bf[j][0], bf[j][1]);
        }

        // ensure tile kt+1 has arrived before next iteration computes it
        if (kt + 2 < 16)      { CP_WAIT1(); }
        else if (kt + 1 < 16) { CP_WAIT0(); }
        __syncthreads();
    }

    float* dst;
    int colBase, rowStride;
    if (EPI == 0) {
        int sq = bx >> 2;
        dst = (sq == 0) ? g_q : (sq == 1) ? g_k : g_v;
        colBase = (bx & 3)*128;
        rowStride = 512;
    } else {
        dst = Cout;
        colBase = bx*128;
        rowStride = Nn;
    }
    #pragma unroll
    for (int i = 0; i < 4; i++) {
        int m0 = by*128 + wm*64 + i*16 + gid;
        #pragma unroll
        for (int j = 0; j < 4; j++) {
            int cl = wn*32 + j*8 + tig*2;
            float bz0 = bias[bx*128 + cl];
            float bz1 = bias[bx*128 + cl + 1];
            float4 d = acc[i][j];
            float2 o0 = make_float2(d.x + bz0, d.y + bz1);
            float2 o1 = make_float2(d.z + bz0, d.w + bz1);
            *(float2*)(dst + (size_t)m0*rowStride + colBase + cl)     = o0;
            *(float2*)(dst + (size_t)(m0+8)*rowStride + colBase + cl) = o1;
        }
    }
}

// ---------------------------------------------------------------------------
// Block-wide inclusive scan (256 threads) via warp shuffles.
// ---------------------------------------------------------------------------
__device__ __forceinline__ unsigned blockScanIncl(unsigned v, unsigned* warpSums, int t)
{
    int lane = t & 31, wid = t >> 5;
    #pragma unroll
    for (int off = 1; off < 32; off <<= 1) {
        unsigned n = __shfl_up_sync(0xffffffffu, v, off);
        if (lane >= off) v += n;
    }
    if (lane == 31) warpSums[wid] = v;
    __syncthreads();
    if (wid == 0) {
        unsigned s = (lane < 8) ? warpSums[lane] : 0u;
        #pragma unroll
        for (int off = 1; off < 8; off <<= 1) {
            unsigned n = __shfl_up_sync(0xffffffffu, s, off);
            if (lane >= off) s += n;
        }
        if (lane < 8) warpSums[lane] = s;
    }
    __syncthreads();
    if (wid > 0) v += warpSums[wid - 1];
    return v;
}

template<int NB>
__device__ __forceinline__ void findThresholdBin(
    const unsigned* hist, unsigned r, unsigned* warpSums, unsigned* sOut, int t)
{
    const int PER = NB / 256;
    unsigned loc[PER];
    unsigned s = 0;
    #pragma unroll
    for (int i = 0; i < PER; i++) { loc[i] = hist[t*PER + i]; s += loc[i]; }
    unsigned incl = blockScanIncl(s, warpSums, t);
    unsigned excl = incl - s;
    if (excl < r && r <= incl) {
        unsigned cum = excl;
        #pragma unroll
        for (int i = 0; i < PER; i++) {
            if (cum + loc[i] >= r) { sOut[0] = t*PER + i; sOut[1] = cum; break; }
            cum += loc[i];
        }
    }
    __syncthreads();
}

// ---------------------------------------------------------------------------
// Selection: pass-1 11-bit radix + exact rank-count on candidates.
// ---------------------------------------------------------------------------
__global__ __launch_bounds__(256) void select_kernel(
    const float* __restrict__ pareto,        // [B,H,NW,N]
    const unsigned char* __restrict__ mask)  // [B,N] bool
{
    __shared__ unsigned hist[2048];
    __shared__ unsigned cand[2048];
    __shared__ unsigned warpSums[8];
    __shared__ unsigned sOut[2];
    __shared__ unsigned sCnt;
    __shared__ unsigned sT, sRR;

    int p = blockIdx.x;
    int nw = p & (NWp-1);
    int b  = p / (Hp*NWp);
    int t  = threadIdx.x;

    const float* prow = pareto + (size_t)p * Np;
    const unsigned char* mrow = mask + (size_t)b * Np;

    unsigned long long mbits = *(const unsigned long long*)(mrow + t*8);
    unsigned key[8];
    #pragma unroll
    for (int v = 0; v < 2; v++) {
        float4 nz = *(const float4*)(prow + t*8 + v*4);
        float noise[4] = {nz.x, nz.y, nz.z, nz.w};
        int ag = nw - (t*2 + v); if (ag < 0) ag = -ag;
        float gridv = (float)ag;
        #pragma unroll
        for (int i = 0; i < 4; i++) {
            float val = gridv - noise[i];
            if ((mbits >> ((v*4 + i)*8)) & 0xFFull) val = 3.402823466e38f;
            unsigned ub = __float_as_uint(val);
            ub ^= ((unsigned)((int)ub >> 31)) | 0x80000000u;
            key[v*4 + i] = ub;
        }
    }

    #pragma unroll
    for (int i = 0; i < 8; i++) hist[t*8 + i] = 0;
    __syncthreads();
    #pragma unroll
    for (int i = 0; i < 8; i++)
        atomicAdd(&hist[key[i] >> 21], 1u);
    __syncthreads();

    unsigned r = 64;
    findThresholdBin<2048>(hist, r, warpSums, sOut, t);
    unsigned bin1 = sOut[0];
    r -= sOut[1];
    __syncthreads();

    if (t == 0) sCnt = 0;
    __syncthreads();
    #pragma unroll
    for (int i = 0; i < 8; i++)
        if ((key[i] >> 21) == bin1)
            cand[atomicAdd(&sCnt, 1u)] = key[i];
    __syncthreads();
    unsigned E = sCnt;

    if (E > 256) {
        #pragma unroll
        for (int i = 0; i < 8; i++) hist[t*8 + i] = 0;
        unsigned kk[8]; int n = 0;
        for (unsigned j = t; j < E; j += 256) kk[n++] = cand[j];
        __syncthreads();
        for (int i = 0; i < n; i++)
            atomicAdd(&hist[(kk[i] >> 10) & 0x7FFu], 1u);
        __syncthreads();
        findThresholdBin<2048>(hist, r, warpSums, sOut, t);
        unsigned bin2 = sOut[0];
        r -= sOut[1];
        __syncthreads();
        if (t == 0) sCnt = 0;
        __syncthreads();
        for (int i = 0; i < n; i++)
            if (((kk[i] >> 10) & 0x7FFu) == bin2)
                cand[atomicAdd(&sCnt, 1u)] = kk[i];
        __syncthreads();
        E = sCnt;
    }

    for (unsigned e = t; e < E; e += 256) {
        unsigned ke = cand[e];
        unsigned less = 0, eq = 0;
        for (unsigned i = 0; i < E; i++) {
            unsigned ki = cand[i];
            less += (ki < ke);
            eq   += (ki == ke);
        }
        if (less < r && r <= less + eq) { sT = ke; sRR = r - less; }
    }
    __syncthreads();
    unsigned T = sT;
    unsigned rr = sRR;

    unsigned lessC = 0, eqC = 0;
    #pragma unroll
    for (int i = 0; i < 8; i++) {
        lessC += (key[i] < T);
        eqC   += (key[i] == T);
    }
    unsigned packed = lessC | (eqC << 16);
    unsigned incl = blockScanIncl(packed, warpSums, t);
    unsigned lb = (incl & 0xFFFFu) - lessC;
    unsigned eb = (incl >> 16)     - eqC;

    int* oidx = g_idx + (size_t)p * KEEP;
    #pragma unroll
    for (int i = 0; i < 8; i++) {
        int j = t*8 + i;
        unsigned k = key[i];
        if (k < T) {
            oidx[lb + min(eb, rr)] = j;
            lb++;
        } else if (k == T) {
            if (eb < rr) oidx[lb + eb] = j;
            eb++;
        }
    }
}

// ---------------------------------------------------------------------------
// Attention: one block per (b,h,nw); 256 threads. q/k/v in [B,N,H,D].
// ---------------------------------------------------------------------------
#define PADR 68
__global__ __launch_bounds__(256) void attn_kernel(
    const float* __restrict__ pos_bias,      // [H,N,N]
    const unsigned char* __restrict__ mask)  // [B,N]
{
    __shared__ int   sidx[KEEP];
    __shared__ float qs[Wp][PADR];
    __shared__ float sd[Wp][PADR];
    __shared__ float pb_s[Wp][PADR];
    __shared__ unsigned char km_s[KEEP];
    __shared__ float partial[4][Wp][Dp];

    int p  = blockIdx.x;
    int nw = p & (NWp-1);
    int bh = p >> 9;
    int h  = bh & (Hp-1);
    int b  = bh >> 3;
    int t  = threadIdx.x;

    if (t < KEEP) sidx[t] = g_idx[(size_t)p * KEEP + t];
    {
        int w = t >> 6, d = t & 63;
        qs[w][d] = g_q[((size_t)(b*Np + nw*Wp + w)*Hp + h)*Dp + d];
    }
    __syncthreads();

    {
        int w = t >> 6, z = t & 63;
        int key = sidx[z];
        pb_s[w][z] = __ldg(pos_bias + ((size_t)h*Np + nw*Wp + w)*Np + key);
        if (t < KEEP) km_s[t] = mask[(size_t)b*Np + sidx[t]];
    }
    __syncthreads();

    const float scale = 0.125f;
    {
        int z = t >> 2, quar = t & 3;
        int row = sidx[z];
        const float* kp = g_k + ((size_t)(b*Np + row)*Hp + h)*Dp + quar*16;
        float4 kv[4];
        #pragma unroll
        for (int i = 0; i < 4; i++) kv[i] = __ldg((const float4*)(kp + i*4));

        bool qm = mask[(size_t)b*Np + nw*Wp + quar] != 0;

        float pw[4] = {0.f, 0.f, 0.f, 0.f};
        #pragma unroll
        for (int i = 0; i < 4; i++) {
            #pragma unroll
            for (int w = 0; w < 4; w++) {
                float4 qv = *(const float4*)&qs[w][quar*16 + i*4];
                pw[w] += qv.x*kv[i].x + qv.y*kv[i].y + qv.z*kv[i].z + qv.w*kv[i].w;
            }
        }
        #pragma unroll
        for (int w = 0; w < 4; w++) {
            pw[w] += __shfl_xor_sync(0xffffffffu, pw[w], 1);
            pw[w] += __shfl_xor_sync(0xffffffffu, pw[w], 2);
        }
        float val = pw[quar]*scale + pb_s[quar][z];
        if (qm && km_s[z]) val = -3.402823466e38f;
        sd[quar][z] = val;
    }
    __syncthreads();

    if (t < 128) {
        int w = t >> 5, lane = t & 31;
        float v0 = sd[w][lane], v1 = sd[w][lane+32];
        float m = fmaxf(v0, v1);
        #pragma unroll
        for (int off = 16; off > 0; off >>= 1)
            m = fmaxf(m, __shfl_xor_sync(0xffffffffu, m, off));
        float e0 = __expf(v0 - m), e1 = __expf(v1 - m);
        float s = e0 + e1;
        #pragma unroll
        for (int off = 16; off > 0; off >>= 1)
            s += __shfl_xor_sync(0xffffffffu, s, off);
        float inv = 1.f / s;
        sd[w][lane]    = e0*inv;
        sd[w][lane+32] = e1*inv;
    }
    __syncthreads();

    {
        int g = t >> 6, d = t & 63;
        const float* vbase = g_v + ((size_t)b*Np*Hp + h)*Dp + d;
        float a0 = 0.f, a1 = 0.f, a2 = 0.f, a3 = 0.f;
        #pragma unroll
        for (int c = 0; c < 4; c++) {
            float4 s0 = *(const float4*)&sd[0][g*16 + c*4];
            float4 s1 = *(const float4*)&sd[1][g*16 + c*4];
            float4 s2 = *(const float4*)&sd[2][g*16 + c*4];
            float4 s3 = *(const float4*)&sd[3][g*16 + c*4];
            float sv0[4] = {s0.x, s0.y, s0.z, s0.w};
            float sv1[4] = {s1.x, s1.y, s1.z, s1.w};
            float sv2[4] = {s2.x, s2.y, s2.z, s2.w};
            float sv3[4] = {s3.x, s3.y, s3.z, s3.w};
            #pragma unroll
            for (int j = 0; j < 4; j++) {
                int z = g*16 + c*4 + j;
                int row = sidx[z];
                float vv = __ldg(vbase + (size_t)row*Hp*Dp);
                a0 += sv0[j] * vv;
                a1 += sv1[j] * vv;
                a2 += sv2[j] * vv;
                a3 += sv3[j] * vv;
            }
        }
        partial[g][0][d] = a0;
        partial[g][1][d] = a1;
        partial[g][2][d] = a2;
        partial[g][3][d] = a3;
    }
    __syncthreads();

    {
        int w = t >> 6, d = t & 63;
        float acc = partial[0][w][d] + partial[1][w][d]
                  + partial[2][w][d] + partial[3][w][d];
        g_attn[((size_t)b*Np + nw*Wp + w)*(Hp*Dp) + h*Dp + d] = to_tf32(acc);
    }
}

// ---------------------------------------------------------------------------
extern "C" void kernel_launch(void* const* d_in, const int* in_sizes, int n_in,
                              void* d_out, int out_size)
{
    const float* x            = (const float*)d_in[0];
    const unsigned char* mask = (const unsigned char*)d_in[1];
    const float* pos_bias     = (const float*)d_in[2];
    const float* pareto       = (const float*)d_in[3];
    const float* Wqkv         = (const float*)d_in[4];
    const float* bqkv         = (const float*)d_in[5];
    const float* Wo           = (const float*)d_in[6];
    const float* bo           = (const float*)d_in[7];
    float* out                = (float*)d_out;

    (void)in_sizes; (void)n_in; (void)out_size;

    static cudaStream_t s2 = nullptr;
    static cudaEvent_t evFork = nullptr, evPerm = nullptr, evJoin = nullptr;
    if (s2 == nullptr) {
        cudaStreamCreateWithFlags(&s2, cudaStreamNonBlocking);
        cudaEventCreateWithFlags(&evFork, cudaEventDisableTiming);
        cudaEventCreateWithFlags(&evPerm, cudaEventDisableTiming);
        cudaEventCreateWithFlags(&evJoin, cudaEventDisableTiming);
        cudaFuncSetAttribute(gemm_tf32_kernel<0>,
            cudaFuncAttributeMaxDynamicSharedMemorySize, GEMM_SMEM);
        cudaFuncSetAttribute(gemm_tf32_kernel<1>,
            cudaFuncAttributeMaxDynamicSharedMemorySize, GEMM_SMEM);
    }

    // Fork side stream: producers for gemm<0>, select, then Wo convert.
    cudaEventRecord(evFork, 0);
    cudaStreamWaitEvent(s2, evFork, 0);
    permW_kernel<<<(Cp*3*Hp*Dp)/256, 256, 0, s2>>>(Wqkv, bqkv);
    convX_kernel<<<(Bp*Np*Cp/4)/256, 256, 0, s2>>>(x);
    cudaEventRecord(evPerm, s2);
    select_kernel<<<Bp*Hp*NWp, 256, 0, s2>>>(pareto, mask);
    convWo_kernel<<<(Cp*Cp/4)/256, 256, 0, s2>>>(Wo);
    cudaEventRecord(evJoin, s2);

    // QKV GEMM (needs g_x32 + g_Wperm).
    cudaStreamWaitEvent(0, evPerm, 0);
    {
        dim3 grid(3*Hp*Dp/128, Bp*Np/128);   // 12 x 64
        gemm_tf32_kernel<0><<<grid, 256, GEMM_SMEM>>>(nullptr, nullptr, 3*Hp*Dp);
    }

    // Attention (needs q/k/v, g_idx; join also covers g_Wo32 for gemm<1>).
    cudaStreamWaitEvent(0, evJoin, 0);
    attn_kernel<<<Bp*Hp*NWp, 256>>>(pos_bias, mask);

    // Output projection.
    {
        dim3 grid(Cp/128, Bp*Np/128);        // 4 x 64
        gemm_tf32_kernel<1><<<grid, 256, GEMM_SMEM>>>(bo, out, Cp);
    }
}

// round 14
// speedup vs baseline: 1.2831x; 1.1725x over previous
#include <cuda_runtime.h>
#include <cuda_fp16.h>
#include <math.h>
#include <stdint.h>

// Problem constants
#define Bp 4
#define Np 2048
#define Cp 512
#define Hp 8
#define Dp 64
#define Wp 4
#define NWp 512
#define KEEP 64

// Scratch (device globals; no allocation allowed)
__device__ float  g_q[Bp*Np*Hp*Dp];        // [B,N,H,D]
__device__ float  g_k[Bp*Np*Hp*Dp];
__device__ float  g_v[Bp*Np*Hp*Dp];
__device__ __half g_attn16[Bp*Np*Hp*Dp];   // [B,N,H*D], fp16 (gemm1 A)
__device__ int    g_idx[Bp*Hp*NWp*KEEP];   // [B,H,NW,64]
__device__ __half g_Wperm16[3*Hp*Dp*Cp];   // Wqkv^T permuted: [u=(s,h,d)][k]
__device__ float  g_bperm[3*Hp*Dp];
__device__ __half g_x16[Bp*Np*Cp];         // x, fp16 (K-major)
__device__ __half g_Wo16[Cp*Cp];           // Wo^T: [n][k], fp16

// ---------------------------------------------------------------------------
// Helpers
// ---------------------------------------------------------------------------
__device__ __forceinline__ void mma_f16(float4& d,
    unsigned a0, unsigned a1, unsigned a2, unsigned a3,
    unsigned b0, unsigned b1)
{
    asm volatile(
        "mma.sync.aligned.m16n8k16.row.col.f32.f16.f16.f32 "
        "{%0,%1,%2,%3}, {%4,%5,%6,%7}, {%8,%9}, {%0,%1,%2,%3};\n"
        : "+f"(d.x), "+f"(d.y), "+f"(d.z), "+f"(d.w)
        : "r"(a0), "r"(a1), "r"(a2), "r"(a3), "r"(b0), "r"(b1));
}

__device__ __forceinline__ uint32_t smem_u32(const void* p) {
    uint32_t a;
    asm("{ .reg .u64 t; cvta.to.shared.u64 t, %1; cvt.u32.u64 %0, t; }"
        : "=r"(a) : "l"(p));
    return a;
}

__device__ __forceinline__ void cp16s(uint32_t dst_smem, const void* src) {
    asm volatile("cp.async.cg.shared.global [%0], [%1], 16;"
                 :: "r"(dst_smem), "l"(src));
}
#define CP_COMMIT() asm volatile("cp.async.commit_group;")
#define CP_WAIT0()  asm volatile("cp.async.wait_group 0;")

// ---------------------------------------------------------------------------
// Producers (side stream, hidden): fp16 conversions + weight transposes.
// ---------------------------------------------------------------------------
__global__ __launch_bounds__(256) void convX_kernel(const float* __restrict__ x)
{
    int i = blockIdx.x*256 + threadIdx.x;
    float4 v = *(const float4*)(x + (size_t)i*4);
    __half2 h0 = __floats2half2_rn(v.x, v.y);
    __half2 h1 = __floats2half2_rn(v.z, v.w);
    uint2 o = make_uint2(*(unsigned*)&h0, *(unsigned*)&h1);
    *(uint2*)(g_x16 + (size_t)i*4) = o;
}

// Transpose+permute Wqkv[k][c] -> g_Wperm16[u(c)][k]; bias -> g_bperm[u].
__global__ void permW_kernel(const float* __restrict__ Wqkv,
                             const float* __restrict__ bqkv)
{
    __shared__ float tile[32][33];
    int tx = threadIdx.x, ty = threadIdx.y;
    int c = blockIdx.x*32 + tx;     // 0..1535
    int k = blockIdx.y*32 + ty;     // 0..511
    tile[ty][tx] = Wqkv[(size_t)k*1536 + c];
    __syncthreads();
    int c2 = blockIdx.x*32 + ty;
    int hd = c2 / 3, s = c2 - hd*3;
    int u = s*512 + hd;
    int k2 = blockIdx.y*32 + tx;
    g_Wperm16[(size_t)u*512 + k2] = __float2half(tile[tx][ty]);
    if (blockIdx.y == 0 && ty == 0) {
        int cc = blockIdx.x*32 + tx;
        int hd2 = cc / 3, s2 = cc - hd2*3;
        g_bperm[s2*512 + hd2] = bqkv[cc];
    }
}

// Transpose Wo[k][n] -> g_Wo16[n][k].
__global__ void convWo_kernel(const float* __restrict__ Wo)
{
    __shared__ float tile[32][33];
    int tx = threadIdx.x, ty = threadIdx.y;
    int n = blockIdx.x*32 + tx;
    int k = blockIdx.y*32 + ty;
    tile[ty][tx] = Wo[(size_t)k*512 + n];
    __syncthreads();
    g_Wo16[(size_t)(blockIdx.x*32 + ty)*512 + blockIdx.y*32 + tx]
        = __float2half(tile[tx][ty]);
}

// ---------------------------------------------------------------------------
// fp16 tensor-core GEMM: C[M,Nn] = A[M,512] @ B^T  (B stored [Nn][512]).
// Tile 128x128x32, 256 threads (2x4 warps, warp tile 64x32), 2-stage cp.async.
// Row stride 40 halfs (80B): 16B-aligned, conflict-free phases.
// EPI=0: A=g_x16, B=g_Wperm16, split epilogue to g_q/g_k/g_v.
// EPI=1: A=g_attn16, B=g_Wo16, writes Cout.
// ---------------------------------------------------------------------------
#define AS_H 40                       // halfs per smem row
#define MAT_HALFS (128*AS_H)          // 5120 halfs per matrix tile
#define STAGE_HALFS (2*MAT_HALFS)     // A + B
#define STAGE_BYTES (STAGE_HALFS*2)   // 20480 B
#define GEMM_SMEM (2*STAGE_BYTES)     // 40960 B

template<int EPI>
__global__ __launch_bounds__(256, 2) void gemm_f16_kernel(
    const float* __restrict__ biasIn,
    float* __restrict__ Cout,
    int Nn)
{
    extern __shared__ __half smh[];
    uint32_t smem_base = smem_u32(smh);

    const __half* A    = (EPI == 0) ? (const __half*)g_x16    : (const __half*)g_attn16;
    const __half* Bw   = (EPI == 0) ? (const __half*)g_Wperm16 : (const __half*)g_Wo16;
    const float*  bias = (EPI == 0) ? (const float*)g_bperm   : biasIn;

    int tid = threadIdx.x;
    int bx = blockIdx.x, by = blockIdx.y;
    int warp = tid >> 5, lane = tid & 31;
    int wm = warp & 1, wn = warp >> 1;
    int gid = lane >> 2, tig = lane & 3;

    float4 acc[4][4];
    #pragma unroll
    for (int i = 0; i < 4; i++)
        #pragma unroll
        for (int j = 0; j < 4; j++) acc[i][j] = make_float4(0.f,0.f,0.f,0.f);

    auto load_tile = [&](int st, int kt) {
        #pragma unroll
        for (int i = 0; i < 2; i++) {
            int f = tid + i*256;            // 0..511
            int row = f >> 2, c16 = f & 3;  // 4 x 16B per 64B row
            uint32_t dA = smem_base + st*STAGE_BYTES + row*80 + c16*16;
            uint32_t dB = dA + MAT_HALFS*2;
            cp16s(dA, A  + (size_t)(by*128 + row)*512 + kt*32 + c16*8);
            cp16s(dB, Bw + (size_t)(bx*128 + row)*512 + kt*32 + c16*8);
        }
        CP_COMMIT();
    };

    load_tile(0, 0);
    CP_WAIT0();
    __syncthreads();

    for (int kt = 0; kt < 16; kt++) {
        if (kt + 1 < 16) load_tile((kt+1)&1, kt+1);

        const __half* Asc = smh + (kt&1)*STAGE_HALFS;
        const __half* Bsc = Asc + MAT_HALFS;
        #pragma unroll
        for (int ks = 0; ks < 2; ks++) {
            int k0 = ks*16;
            unsigned af[4][4], bf[4][2];
            #pragma unroll
            for (int i = 0; i < 4; i++) {
                int r = wm*64 + i*16 + gid;
                af[i][0] = *(const unsigned*)&Asc[ r    *AS_H + k0 + tig*2];
                af[i][1] = *(const unsigned*)&Asc[(r+8)*AS_H + k0 + tig*2];
                af[i][2] = *(const unsigned*)&Asc[ r    *AS_H + k0 + tig*2 + 8];
                af[i][3] = *(const unsigned*)&Asc[(r+8)*AS_H + k0 + tig*2 + 8];
            }
            #pragma unroll
            for (int j = 0; j < 4; j++) {
                int c = wn*32 + j*8 + gid;
                bf[j][0] = *(const unsigned*)&Bsc[c*AS_H + k0 + tig*2];
                bf[j][1] = *(const unsigned*)&Bsc[c*AS_H + k0 + tig*2 + 8];
            }
            #pragma unroll
            for (int i = 0; i < 4; i++)
                #pragma unroll
                for (int j = 0; j < 4; j++)
                    mma_f16(acc[i][j], af[i][0], af[i][1], af[i][2], af[i][3],
                            bf[j][0], bf[j][1]);
        }

        if (kt + 1 < 16) CP_WAIT0();
        __syncthreads();
    }

    float* dst;
    int colBase, rowStride;
    if (EPI == 0) {
        int sq = bx >> 2;
        dst = (sq == 0) ? g_q : (sq == 1) ? g_k : g_v;
        colBase = (bx & 3)*128;
        rowStride = 512;
    } else {
        dst = Cout;
        colBase = bx*128;
        rowStride = Nn;
    }
    #pragma unroll
    for (int i = 0; i < 4; i++) {
        int m0 = by*128 + wm*64 + i*16 + gid;
        #pragma unroll
        for (int j = 0; j < 4; j++) {
            int cl = wn*32 + j*8 + tig*2;
            float bz0 = bias[bx*128 + cl];
            float bz1 = bias[bx*128 + cl + 1];
            float4 d = acc[i][j];
            float2 o0 = make_float2(d.x + bz0, d.y + bz1);
            float2 o1 = make_float2(d.z + bz0, d.w + bz1);
            *(float2*)(dst + (size_t)m0*rowStride + colBase + cl)     = o0;
            *(float2*)(dst + (size_t)(m0+8)*rowStride + colBase + cl) = o1;
        }
    }
}

// ---------------------------------------------------------------------------
// Block-wide inclusive scan (256 threads) via warp shuffles.
// ---------------------------------------------------------------------------
__device__ __forceinline__ unsigned blockScanIncl(unsigned v, unsigned* warpSums, int t)
{
    int lane = t & 31, wid = t >> 5;
    #pragma unroll
    for (int off = 1; off < 32; off <<= 1) {
        unsigned n = __shfl_up_sync(0xffffffffu, v, off);
        if (lane >= off) v += n;
    }
    if (lane == 31) warpSums[wid] = v;
    __syncthreads();
    if (wid == 0) {
        unsigned s = (lane < 8) ? warpSums[lane] : 0u;
        #pragma unroll
        for (int off = 1; off < 8; off <<= 1) {
            unsigned n = __shfl_up_sync(0xffffffffu, s, off);
            if (lane >= off) s += n;
        }
        if (lane < 8) warpSums[lane] = s;
    }
    __syncthreads();
    if (wid > 0) v += warpSums[wid - 1];
    return v;
}

template<int NB>
__device__ __forceinline__ void findThresholdBin(
    const unsigned* hist, unsigned r, unsigned* warpSums, unsigned* sOut, int t)
{
    const int PER = NB / 256;
    unsigned loc[PER];
    unsigned s = 0;
    #pragma unroll
    for (int i = 0; i < PER; i++) { loc[i] = hist[t*PER + i]; s += loc[i]; }
    unsigned incl = blockScanIncl(s, warpSums, t);
    unsigned excl = incl - s;
    if (excl < r && r <= incl) {
        unsigned cum = excl;
        #pragma unroll
        for (int i = 0; i < PER; i++) {
            if (cum + loc[i] >= r) { sOut[0] = t*PER + i; sOut[1] = cum; break; }
            cum += loc[i];
        }
    }
    __syncthreads();
}

// ---------------------------------------------------------------------------
// Selection: pass-1 11-bit radix + exact rank-count on candidates.
// ---------------------------------------------------------------------------
__global__ __launch_bounds__(256) void select_kernel(
    const float* __restrict__ pareto,
    const unsigned char* __restrict__ mask)
{
    __shared__ unsigned hist[2048];
    __shared__ unsigned cand[2048];
    __shared__ unsigned warpSums[8];
    __shared__ unsigned sOut[2];
    __shared__ unsigned sCnt;
    __shared__ unsigned sT, sRR;

    int p = blockIdx.x;
    int nw = p & (NWp-1);
    int b  = p / (Hp*NWp);
    int t  = threadIdx.x;

    const float* prow = pareto + (size_t)p * Np;
    const unsigned char* mrow = mask + (size_t)b * Np;

    unsigned long long mbits = *(const unsigned long long*)(mrow + t*8);
    unsigned key[8];
    #pragma unroll
    for (int v = 0; v < 2; v++) {
        float4 nz = *(const float4*)(prow + t*8 + v*4);
        float noise[4] = {nz.x, nz.y, nz.z, nz.w};
        int ag = nw - (t*2 + v); if (ag < 0) ag = -ag;
        float gridv = (float)ag;
        #pragma unroll
        for (int i = 0; i < 4; i++) {
            float val = gridv - noise[i];
            if ((mbits >> ((v*4 + i)*8)) & 0xFFull) val = 3.402823466e38f;
            unsigned ub = __float_as_uint(val);
            ub ^= ((unsigned)((int)ub >> 31)) | 0x80000000u;
            key[v*4 + i] = ub;
        }
    }

    #pragma unroll
    for (int i = 0; i < 8; i++) hist[t*8 + i] = 0;
    __syncthreads();
    #pragma unroll
    for (int i = 0; i < 8; i++)
        atomicAdd(&hist[key[i] >> 21], 1u);
    __syncthreads();

    unsigned r = 64;
    findThresholdBin<2048>(hist, r, warpSums, sOut, t);
    unsigned bin1 = sOut[0];
    r -= sOut[1];
    __syncthreads();

    if (t == 0) sCnt = 0;
    __syncthreads();
    #pragma unroll
    for (int i = 0; i < 8; i++)
        if ((key[i] >> 21) == bin1)
            cand[atomicAdd(&sCnt, 1u)] = key[i];
    __syncthreads();
    unsigned E = sCnt;

    if (E > 256) {
        #pragma unroll
        for (int i = 0; i < 8; i++) hist[t*8 + i] = 0;
        unsigned kk[8]; int n = 0;
        for (unsigned j = t; j < E; j += 256) kk[n++] = cand[j];
        __syncthreads();
        for (int i = 0; i < n; i++)
            atomicAdd(&hist[(kk[i] >> 10) & 0x7FFu], 1u);
        __syncthreads();
        findThresholdBin<2048>(hist, r, warpSums, sOut, t);
        unsigned bin2 = sOut[0];
        r -= sOut[1];
        __syncthreads();
        if (t == 0) sCnt = 0;
        __syncthreads();
        for (int i = 0; i < n; i++)
            if (((kk[i] >> 10) & 0x7FFu) == bin2)
                cand[atomicAdd(&sCnt, 1u)] = kk[i];
        __syncthreads();
        E = sCnt;
    }

    for (unsigned e = t; e < E; e += 256) {
        unsigned ke = cand[e];
        unsigned less = 0, eq = 0;
        for (unsigned i = 0; i < E; i++) {
            unsigned ki = cand[i];
            less += (ki < ke);
            eq   += (ki == ke);
        }
        if (less < r && r <= less + eq) { sT = ke; sRR = r - less; }
    }
    __syncthreads();
    unsigned T = sT;
    unsigned rr = sRR;

    unsigned lessC = 0, eqC = 0;
    #pragma unroll
    for (int i = 0; i < 8; i++) {
        lessC += (key[i] < T);
        eqC   += (key[i] == T);
    }
    unsigned packed = lessC | (eqC << 16);
    unsigned incl = blockScanIncl(packed, warpSums, t);
    unsigned lb = (incl & 0xFFFFu) - lessC;
    unsigned eb = (incl >> 16)     - eqC;

    int* oidx = g_idx + (size_t)p * KEEP;
    #pragma unroll
    for (int i = 0; i < 8; i++) {
        int j = t*8 + i;
        unsigned k = key[i];
        if (k < T) {
            oidx[lb + min(eb, rr)] = j;
            lb++;
        } else if (k == T) {
            if (eb < rr) oidx[lb + eb] = j;
            eb++;
        }
    }
}

// ---------------------------------------------------------------------------
// Attention (R10-best); epilogue converts to fp16 for gemm1.
// ---------------------------------------------------------------------------
#define PADR 68
__global__ __launch_bounds__(256) void attn_kernel(
    const float* __restrict__ pos_bias,
    const unsigned char* __restrict__ mask)
{
    __shared__ int   sidx[KEEP];
    __shared__ float qs[Wp][PADR];
    __shared__ float sd[Wp][PADR];
    __shared__ float pb_s[Wp][PADR];
    __shared__ unsigned char km_s[KEEP];
    __shared__ float partial[4][Wp][Dp];

    int p  = blockIdx.x;
    int nw = p & (NWp-1);
    int bh = p >> 9;
    int h  = bh & (Hp-1);
    int b  = bh >> 3;
    int t  = threadIdx.x;

    if (t < KEEP) sidx[t] = g_idx[(size_t)p * KEEP + t];
    {
        int w = t >> 6, d = t & 63;
        qs[w][d] = g_q[((size_t)(b*Np + nw*Wp + w)*Hp + h)*Dp + d];
    }
    __syncthreads();

    {
        int w = t >> 6, z = t & 63;
        int key = sidx[z];
        pb_s[w][z] = __ldg(pos_bias + ((size_t)h*Np + nw*Wp + w)*Np + key);
        if (t < KEEP) km_s[t] = mask[(size_t)b*Np + sidx[t]];
    }
    __syncthreads();

    const float scale = 0.125f;
    {
        int z = t >> 2, quar = t & 3;
        int row = sidx[z];
        const float* kp = g_k + ((size_t)(b*Np + row)*Hp + h)*Dp + quar*16;
        float4 kv[4];
        #pragma unroll
        for (int i = 0; i < 4; i++) kv[i] = __ldg((const float4*)(kp + i*4));

        bool qm = mask[(size_t)b*Np + nw*Wp + quar] != 0;

        float pw[4] = {0.f, 0.f, 0.f, 0.f};
        #pragma unroll
        for (int i = 0; i < 4; i++) {
            #pragma unroll
            for (int w = 0; w < 4; w++) {
                float4 qv = *(const float4*)&qs[w][quar*16 + i*4];
                pw[w] += qv.x*kv[i].x + qv.y*kv[i].y + qv.z*kv[i].z + qv.w*kv[i].w;
            }
        }
        #pragma unroll
        for (int w = 0; w < 4; w++) {
            pw[w] += __shfl_xor_sync(0xffffffffu, pw[w], 1);
            pw[w] += __shfl_xor_sync(0xffffffffu, pw[w], 2);
        }
        float val = pw[quar]*scale + pb_s[quar][z];
        if (qm && km_s[z]) val = -3.402823466e38f;
        sd[quar][z] = val;
    }
    __syncthreads();

    if (t < 128) {
        int w = t >> 5, lane = t & 31;
        float v0 = sd[w][lane], v1 = sd[w][lane+32];
        float m = fmaxf(v0, v1);
        #pragma unroll
        for (int off = 16; off > 0; off >>= 1)
            m = fmaxf(m, __shfl_xor_sync(0xffffffffu, m, off));
        float e0 = __expf(v0 - m), e1 = __expf(v1 - m);
        float s = e0 + e1;
        #pragma unroll
        for (int off = 16; off > 0; off >>= 1)
            s += __shfl_xor_sync(0xffffffffu, s, off);
        float inv = 1.f / s;
        sd[w][lane]    = e0*inv;
        sd[w][lane+32] = e1*inv;
    }
    __syncthreads();

    {
        int g = t >> 6, d = t & 63;
        const float* vbase = g_v + ((size_t)b*Np*Hp + h)*Dp + d;
        float a0 = 0.f, a1 = 0.f, a2 = 0.f, a3 = 0.f;
        #pragma unroll
        for (int c = 0; c < 4; c++) {
            float4 s0 = *(const float4*)&sd[0][g*16 + c*4];
            float4 s1 = *(const float4*)&sd[1][g*16 + c*4];
            float4 s2 = *(const float4*)&sd[2][g*16 + c*4];
            float4 s3 = *(const float4*)&sd[3][g*16 + c*4];
            float sv0[4] = {s0.x, s0.y, s0.z, s0.w};
            float sv1[4] = {s1.x, s1.y, s1.z, s1.w};
            float sv2[4] = {s2.x, s2.y, s2.z, s2.w};
            float sv3[4] = {s3.x, s3.y, s3.z, s3.w};
            #pragma unroll
            for (int j = 0; j < 4; j++) {
                int z = g*16 + c*4 + j;
                int row = sidx[z];
                float vv = __ldg(vbase + (size_t)row*Hp*Dp);
                a0 += sv0[j] * vv;
                a1 += sv1[j] * vv;
                a2 += sv2[j] * vv;
                a3 += sv3[j] * vv;
            }
        }
        partial[g][0][d] = a0;
        partial[g][1][d] = a1;
        partial[g][2][d] = a2;
        partial[g][3][d] = a3;
    }
    __syncthreads();

    {
        int w = t >> 6, d = t & 63;
        float acc = partial[0][w][d] + partial[1][w][d]
                  + partial[2][w][d] + partial[3][w][d];
        g_attn16[((size_t)b*Np + nw*Wp + w)*(Hp*Dp) + h*Dp + d] = __float2half(acc);
    }
}

// ---------------------------------------------------------------------------
extern "C" void kernel_launch(void* const* d_in, const int* in_sizes, int n_in,
                              void* d_out, int out_size)
{
    const float* x            = (const float*)d_in[0];
    const unsigned char* mask = (const unsigned char*)d_in[1];
    const float* pos_bias     = (const float*)d_in[2];
    const float* pareto       = (const float*)d_in[3];
    const float* Wqkv         = (const float*)d_in[4];
    const float* bqkv         = (const float*)d_in[5];
    const float* Wo           = (const float*)d_in[6];
    const float* bo           = (const float*)d_in[7];
    float* out                = (float*)d_out;

    (void)in_sizes; (void)n_in; (void)out_size;

    static cudaStream_t s2 = nullptr;
    static cudaEvent_t evFork = nullptr, evPerm = nullptr, evJoin = nullptr;
    if (s2 == nullptr) {
        cudaStreamCreateWithFlags(&s2, cudaStreamNonBlocking);
        cudaEventCreateWithFlags(&evFork, cudaEventDisableTiming);
        cudaEventCreateWithFlags(&evPerm, cudaEventDisableTiming);
        cudaEventCreateWithFlags(&evJoin, cudaEventDisableTiming);
        cudaFuncSetAttribute(gemm_f16_kernel<0>,
            cudaFuncAttributeMaxDynamicSharedMemorySize, GEMM_SMEM);
        cudaFuncSetAttribute(gemm_f16_kernel<1>,
            cudaFuncAttributeMaxDynamicSharedMemorySize, GEMM_SMEM);
    }

    // Side stream: producers for gemm0, select, then Wo transpose.
    cudaEventRecord(evFork, 0);
    cudaStreamWaitEvent(s2, evFork, 0);
    permW_kernel<<<dim3(48,16), dim3(32,32), 0, s2>>>(Wqkv, bqkv);
    convX_kernel<<<(Bp*Np*Cp/4)/256, 256, 0, s2>>>(x);
    cudaEventRecord(evPerm, s2);
    select_kernel<<<Bp*Hp*NWp, 256, 0, s2>>>(pareto, mask);
    convWo_kernel<<<dim3(16,16), dim3(32,32), 0, s2>>>(Wo);
    cudaEventRecord(evJoin, s2);

    // QKV GEMM (fp16 tensor cores).
    cudaStreamWaitEvent(0, evPerm, 0);
    {
        dim3 grid(3*Hp*Dp/128, Bp*Np/128);   // 12 x 64
        gemm_f16_kernel<0><<<grid, 256, GEMM_SMEM>>>(nullptr, nullptr, 3*Hp*Dp);
    }

    // Attention.
    cudaStreamWaitEvent(0, evJoin, 0);
    attn_kernel<<<Bp*Hp*NWp, 256>>>(pos_bias, mask);

    // Output projection (fp16 tensor cores).
    {
        dim3 grid(Cp/128, Bp*Np/128);        // 4 x 64
        gemm_f16_kernel<1><<<grid, 256, GEMM_SMEM>>>(bo, out, Cp);
    }
}

// round 15
// speedup vs baseline: 1.3533x; 1.0547x over previous
#include <cuda_runtime.h>
#include <cuda_fp16.h>
#include <math.h>
#include <stdint.h>

// Problem constants
#define Bp 4
#define Np 2048
#define Cp 512
#define Hp 8
#define Dp 64
#define Wp 4
#define NWp 512
#define KEEP 64

// Scratch (device globals; no allocation allowed)
__device__ __half g_q16[Bp*Np*Hp*Dp];      // [B,N,H,D] fp16
__device__ __half g_k16[Bp*Np*Hp*Dp];
__device__ __half g_v16[Bp*Np*Hp*Dp];
__device__ __half g_attn16[Bp*Np*Hp*Dp];   // [B,N,H*D], fp16 (gemm1 A)
__device__ int    g_idx[Bp*Hp*NWp*KEEP];   // [B,H,NW,64]
__device__ __half g_Wperm16[3*Hp*Dp*Cp];   // Wqkv^T permuted: [u=(s,h,d)][k]
__device__ float  g_bperm[3*Hp*Dp];
__device__ __half g_x16[Bp*Np*Cp];         // x, fp16 (K-major)
__device__ __half g_Wo16[Cp*Cp];           // Wo^T: [n][k], fp16

// ---------------------------------------------------------------------------
// Helpers
// ---------------------------------------------------------------------------
__device__ __forceinline__ void mma_f16(float4& d,
    unsigned a0, unsigned a1, unsigned a2, unsigned a3,
    unsigned b0, unsigned b1)
{
    asm volatile(
        "mma.sync.aligned.m16n8k16.row.col.f32.f16.f16.f32 "
        "{%0,%1,%2,%3}, {%4,%5,%6,%7}, {%8,%9}, {%0,%1,%2,%3};\n"
        : "+f"(d.x), "+f"(d.y), "+f"(d.z), "+f"(d.w)
        : "r"(a0), "r"(a1), "r"(a2), "r"(a3), "r"(b0), "r"(b1));
}

__device__ __forceinline__ uint32_t smem_u32(const void* p) {
    uint32_t a;
    asm("{ .reg .u64 t; cvta.to.shared.u64 t, %1; cvt.u32.u64 %0, t; }"
        : "=r"(a) : "l"(p));
    return a;
}

__device__ __forceinline__ void cp16s(uint32_t dst_smem, const void* src) {
    asm volatile("cp.async.cg.shared.global [%0], [%1], 16;"
                 :: "r"(dst_smem), "l"(src));
}
#define CP_COMMIT() asm volatile("cp.async.commit_group;")
#define CP_WAIT0()  asm volatile("cp.async.wait_group 0;")

// ---------------------------------------------------------------------------
// Producers (side stream, hidden): fp16 conversions + weight transposes.
// ---------------------------------------------------------------------------
__global__ __launch_bounds__(256) void convX_kernel(const float* __restrict__ x)
{
    int i = blockIdx.x*256 + threadIdx.x;
    float4 v = *(const float4*)(x + (size_t)i*4);
    __half2 h0 = __floats2half2_rn(v.x, v.y);
    __half2 h1 = __floats2half2_rn(v.z, v.w);
    uint2 o = make_uint2(*(unsigned*)&h0, *(unsigned*)&h1);
    *(uint2*)(g_x16 + (size_t)i*4) = o;
}

__global__ void permW_kernel(const float* __restrict__ Wqkv,
                             const float* __restrict__ bqkv)
{
    __shared__ float tile[32][33];
    int tx = threadIdx.x, ty = threadIdx.y;
    int c = blockIdx.x*32 + tx;     // 0..1535
    int k = blockIdx.y*32 + ty;     // 0..511
    tile[ty][tx] = Wqkv[(size_t)k*1536 + c];
    __syncthreads();
    int c2 = blockIdx.x*32 + ty;
    int hd = c2 / 3, s = c2 - hd*3;
    int u = s*512 + hd;
    int k2 = blockIdx.y*32 + tx;
    g_Wperm16[(size_t)u*512 + k2] = __float2half(tile[tx][ty]);
    if (blockIdx.y == 0 && ty == 0) {
        int cc = blockIdx.x*32 + tx;
        int hd2 = cc / 3, s2 = cc - hd2*3;
        g_bperm[s2*512 + hd2] = bqkv[cc];
    }
}

__global__ void convWo_kernel(const float* __restrict__ Wo)
{
    __shared__ float tile[32][33];
    int tx = threadIdx.x, ty = threadIdx.y;
    int n = blockIdx.x*32 + tx;
    int k = blockIdx.y*32 + ty;
    tile[ty][tx] = Wo[(size_t)k*512 + n];
    __syncthreads();
    g_Wo16[(size_t)(blockIdx.x*32 + ty)*512 + blockIdx.y*32 + tx]
        = __float2half(tile[tx][ty]);
}

// ---------------------------------------------------------------------------
// fp16 tensor-core GEMM: C[M,Nn] = A[M,512] @ B^T (B stored [Nn][512]).
// Tile 128x128x32, 256 threads, 2-stage cp.async, 80B smem rows.
// EPI=0: split epilogue to g_q16/g_k16/g_v16 (fp16 stores).
// EPI=1: writes Cout (fp32).
// ---------------------------------------------------------------------------
#define AS_H 40
#define MAT_HALFS (128*AS_H)
#define STAGE_HALFS (2*MAT_HALFS)
#define STAGE_BYTES (STAGE_HALFS*2)   // 20480 B
#define GEMM_SMEM (2*STAGE_BYTES)     // 40960 B

template<int EPI>
__global__ __launch_bounds__(256, 2) void gemm_f16_kernel(
    const float* __restrict__ biasIn,
    float* __restrict__ Cout,
    int Nn)
{
    extern __shared__ __half smh[];
    uint32_t smem_base = smem_u32(smh);

    const __half* A    = (EPI == 0) ? (const __half*)g_x16    : (const __half*)g_attn16;
    const __half* Bw   = (EPI == 0) ? (const __half*)g_Wperm16 : (const __half*)g_Wo16;
    const float*  bias = (EPI == 0) ? (const float*)g_bperm   : biasIn;

    int tid = threadIdx.x;
    int bx = blockIdx.x, by = blockIdx.y;
    int warp = tid >> 5, lane = tid & 31;
    int wm = warp & 1, wn = warp >> 1;
    int gid = lane >> 2, tig = lane & 3;

    float4 acc[4][4];
    #pragma unroll
    for (int i = 0; i < 4; i++)
        #pragma unroll
        for (int j = 0; j < 4; j++) acc[i][j] = make_float4(0.f,0.f,0.f,0.f);

    auto load_tile = [&](int st, int kt) {
        #pragma unroll
        for (int i = 0; i < 2; i++) {
            int f = tid + i*256;
            int row = f >> 2, c16 = f & 3;
            uint32_t dA = smem_base + st*STAGE_BYTES + row*80 + c16*16;
            uint32_t dB = dA + MAT_HALFS*2;
            cp16s(dA, A  + (size_t)(by*128 + row)*512 + kt*32 + c16*8);
            cp16s(dB, Bw + (size_t)(bx*128 + row)*512 + kt*32 + c16*8);
        }
        CP_COMMIT();
    };

    load_tile(0, 0);
    CP_WAIT0();
    __syncthreads();

    for (int kt = 0; kt < 16; kt++) {
        if (kt + 1 < 16) load_tile((kt+1)&1, kt+1);

        const __half* Asc = smh + (kt&1)*STAGE_HALFS;
        const __half* Bsc = Asc + MAT_HALFS;
        #pragma unroll
        for (int ks = 0; ks < 2; ks++) {
            int k0 = ks*16;
            unsigned af[4][4], bf[4][2];
            #pragma unroll
            for (int i = 0; i < 4; i++) {
                int r = wm*64 + i*16 + gid;
                af[i][0] = *(const unsigned*)&Asc[ r    *AS_H + k0 + tig*2];
                af[i][1] = *(const unsigned*)&Asc[(r+8)*AS_H + k0 + tig*2];
                af[i][2] = *(const unsigned*)&Asc[ r    *AS_H + k0 + tig*2 + 8];
                af[i][3] = *(const unsigned*)&Asc[(r+8)*AS_H + k0 + tig*2 + 8];
            }
            #pragma unroll
            for (int j = 0; j < 4; j++) {
                int c = wn*32 + j*8 + gid;
                bf[j][0] = *(const unsigned*)&Bsc[c*AS_H + k0 + tig*2];
                bf[j][1] = *(const unsigned*)&Bsc[c*AS_H + k0 + tig*2 + 8];
            }
            #pragma unroll
            for (int i = 0; i < 4; i++)
                #pragma unroll
                for (int j = 0; j < 4; j++)
                    mma_f16(acc[i][j], af[i][0], af[i][1], af[i][2], af[i][3],
                            bf[j][0], bf[j][1]);
        }

        if (kt + 1 < 16) CP_WAIT0();
        __syncthreads();
    }

    if (EPI == 0) {
        int sq = bx >> 2;
        __half* dst = (sq == 0) ? g_q16 : (sq == 1) ? g_k16 : g_v16;
        int colBase = (bx & 3)*128;
        #pragma unroll
        for (int i = 0; i < 4; i++) {
            int m0 = by*128 + wm*64 + i*16 + gid;
            #pragma unroll
            for (int j = 0; j < 4; j++) {
                int cl = wn*32 + j*8 + tig*2;
                float bz0 = bias[bx*128 + cl];
                float bz1 = bias[bx*128 + cl + 1];
                float4 d = acc[i][j];
                __half2 h0 = __floats2half2_rn(d.x + bz0, d.y + bz1);
                __half2 h1 = __floats2half2_rn(d.z + bz0, d.w + bz1);
                *(__half2*)(dst + (size_t)m0*512 + colBase + cl)     = h0;
                *(__half2*)(dst + (size_t)(m0+8)*512 + colBase + cl) = h1;
            }
        }
    } else {
        #pragma unroll
        for (int i = 0; i < 4; i++) {
            int m0 = by*128 + wm*64 + i*16 + gid;
            #pragma unroll
            for (int j = 0; j < 4; j++) {
                int cl = wn*32 + j*8 + tig*2;
                float bz0 = bias[bx*128 + cl];
                float bz1 = bias[bx*128 + cl + 1];
                float4 d = acc[i][j];
                float2 o0 = make_float2(d.x + bz0, d.y + bz1);
                float2 o1 = make_float2(d.z + bz0, d.w + bz1);
                *(float2*)(Cout + (size_t)m0*Nn + bx*128 + cl)     = o0;
                *(float2*)(Cout + (size_t)(m0+8)*Nn + bx*128 + cl) = o1;
            }
        }
    }
}

// ---------------------------------------------------------------------------
// Block-wide inclusive scan (256 threads) via warp shuffles.
// ---------------------------------------------------------------------------
__device__ __forceinline__ unsigned blockScanIncl(unsigned v, unsigned* warpSums, int t)
{
    int lane = t & 31, wid = t >> 5;
    #pragma unroll
    for (int off = 1; off < 32; off <<= 1) {
        unsigned n = __shfl_up_sync(0xffffffffu, v, off);
        if (lane >= off) v += n;
    }
    if (lane == 31) warpSums[wid] = v;
    __syncthreads();
    if (wid == 0) {
        unsigned s = (lane < 8) ? warpSums[lane] : 0u;
        #pragma unroll
        for (int off = 1; off < 8; off <<= 1) {
            unsigned n = __shfl_up_sync(0xffffffffu, s, off);
            if (lane >= off) s += n;
        }
        if (lane < 8) warpSums[lane] = s;
    }
    __syncthreads();
    if (wid > 0) v += warpSums[wid - 1];
    return v;
}

template<int NB>
__device__ __forceinline__ void findThresholdBin(
    const unsigned* hist, unsigned r, unsigned* warpSums, unsigned* sOut, int t)
{
    const int PER = NB / 256;
    unsigned loc[PER];
    unsigned s = 0;
    #pragma unroll
    for (int i = 0; i < PER; i++) { loc[i] = hist[t*PER + i]; s += loc[i]; }
    unsigned incl = blockScanIncl(s, warpSums, t);
    unsigned excl = incl - s;
    if (excl < r && r <= incl) {
        unsigned cum = excl;
        #pragma unroll
        for (int i = 0; i < PER; i++) {
            if (cum + loc[i] >= r) { sOut[0] = t*PER + i; sOut[1] = cum; break; }
            cum += loc[i];
        }
    }
    __syncthreads();
}

// ---------------------------------------------------------------------------
// Selection: pass-1 11-bit radix + exact rank-count on candidates.
// ---------------------------------------------------------------------------
__global__ __launch_bounds__(256) void select_kernel(
    const float* __restrict__ pareto,
    const unsigned char* __restrict__ mask)
{
    __shared__ unsigned hist[2048];
    __shared__ unsigned cand[2048];
    __shared__ unsigned warpSums[8];
    __shared__ unsigned sOut[2];
    __shared__ unsigned sCnt;
    __shared__ unsigned sT, sRR;

    int p = blockIdx.x;
    int nw = p & (NWp-1);
    int b  = p / (Hp*NWp);
    int t  = threadIdx.x;

    const float* prow = pareto + (size_t)p * Np;
    const unsigned char* mrow = mask + (size_t)b * Np;

    unsigned long long mbits = *(const unsigned long long*)(mrow + t*8);
    unsigned key[8];
    #pragma unroll
    for (int v = 0; v < 2; v++) {
        float4 nz = *(const float4*)(prow + t*8 + v*4);
        float noise[4] = {nz.x, nz.y, nz.z, nz.w};
        int ag = nw - (t*2 + v); if (ag < 0) ag = -ag;
        float gridv = (float)ag;
        #pragma unroll
        for (int i = 0; i < 4; i++) {
            float val = gridv - noise[i];
            if ((mbits >> ((v*4 + i)*8)) & 0xFFull) val = 3.402823466e38f;
            unsigned ub = __float_as_uint(val);
            ub ^= ((unsigned)((int)ub >> 31)) | 0x80000000u;
            key[v*4 + i] = ub;
        }
    }

    #pragma unroll
    for (int i = 0; i < 8; i++) hist[t*8 + i] = 0;
    __syncthreads();
    #pragma unroll
    for (int i = 0; i < 8; i++)
        atomicAdd(&hist[key[i] >> 21], 1u);
    __syncthreads();

    unsigned r = 64;
    findThresholdBin<2048>(hist, r, warpSums, sOut, t);
    unsigned bin1 = sOut[0];
    r -= sOut[1];
    __syncthreads();

    if (t == 0) sCnt = 0;
    __syncthreads();
    #pragma unroll
    for (int i = 0; i < 8; i++)
        if ((key[i] >> 21) == bin1)
            cand[atomicAdd(&sCnt, 1u)] = key[i];
    __syncthreads();
    unsigned E = sCnt;

    if (E > 256) {
        #pragma unroll
        for (int i = 0; i < 8; i++) hist[t*8 + i] = 0;
        unsigned kk[8]; int n = 0;
        for (unsigned j = t; j < E; j += 256) kk[n++] = cand[j];
        __syncthreads();
        for (int i = 0; i < n; i++)
            atomicAdd(&hist[(kk[i] >> 10) & 0x7FFu], 1u);
        __syncthreads();
        findThresholdBin<2048>(hist, r, warpSums, sOut, t);
        unsigned bin2 = sOut[0];
        r -= sOut[1];
        __syncthreads();
        if (t == 0) sCnt = 0;
        __syncthreads();
        for (int i = 0; i < n; i++)
            if (((kk[i] >> 10) & 0x7FFu) == bin2)
                cand[atomicAdd(&sCnt, 1u)] = kk[i];
        __syncthreads();
        E = sCnt;
    }

    for (unsigned e = t; e < E; e += 256) {
        unsigned ke = cand[e];
        unsigned less = 0, eq = 0;
        for (unsigned i = 0; i < E; i++) {
            unsigned ki = cand[i];
            less += (ki < ke);
            eq   += (ki == ke);
        }
        if (less < r && r <= less + eq) { sT = ke; sRR = r - less; }
    }
    __syncthreads();
    unsigned T = sT;
    unsigned rr = sRR;

    unsigned lessC = 0, eqC = 0;
    #pragma unroll
    for (int i = 0; i < 8; i++) {
        lessC += (key[i] < T);
        eqC   += (key[i] == T);
    }
    unsigned packed = lessC | (eqC << 16);
    unsigned incl = blockScanIncl(packed, warpSums, t);
    unsigned lb = (incl & 0xFFFFu) - lessC;
    unsigned eb = (incl >> 16)     - eqC;

    int* oidx = g_idx + (size_t)p * KEEP;
    #pragma unroll
    for (int i = 0; i < 8; i++) {
        int j = t*8 + i;
        unsigned k = key[i];
        if (k < T) {
            oidx[lb + min(eb, rr)] = j;
            lb++;
        } else if (k == T) {
            if (eb < rr) oidx[lb + eb] = j;
            eb++;
        }
    }
}

// ---------------------------------------------------------------------------
// Attention: q/k/v fp16 in [B,N,H,D]; fp32 accumulate; writes g_attn16.
// ---------------------------------------------------------------------------
#define PADR 68
__global__ __launch_bounds__(256) void attn_kernel(
    const float* __restrict__ pos_bias,
    const unsigned char* __restrict__ mask)
{
    __shared__ int   sidx[KEEP];
    __shared__ float qs[Wp][PADR];
    __shared__ float sd[Wp][PADR];
    __shared__ float pb_s[Wp][PADR];
    __shared__ unsigned char km_s[KEEP];
    __shared__ float partial[4][Wp][Dp];

    int p  = blockIdx.x;
    int nw = p & (NWp-1);
    int bh = p >> 9;
    int h  = bh & (Hp-1);
    int b  = bh >> 3;
    int t  = threadIdx.x;

    if (t < KEEP) sidx[t] = g_idx[(size_t)p * KEEP + t];
    {
        int w = t >> 6, d = t & 63;
        qs[w][d] = __half2float(
            g_q16[((size_t)(b*Np + nw*Wp + w)*Hp + h)*Dp + d]);
    }
    __syncthreads();

    {
        int w = t >> 6, z = t & 63;
        int key = sidx[z];
        pb_s[w][z] = __ldg(pos_bias + ((size_t)h*Np + nw*Wp + w)*Np + key);
        if (t < KEEP) km_s[t] = mask[(size_t)b*Np + sidx[t]];
    }
    __syncthreads();

    const float scale = 0.125f;
    {
        int z = t >> 2, quar = t & 3;
        int row = sidx[z];
        const __half* kp = g_k16 + ((size_t)(b*Np + row)*Hp + h)*Dp + quar*16;
        uint4 kraw0 = __ldg((const uint4*)kp);
        uint4 kraw1 = __ldg((const uint4*)(kp + 8));
        __half2 kh[8];
        kh[0] = *(__half2*)&kraw0.x; kh[1] = *(__half2*)&kraw0.y;
        kh[2] = *(__half2*)&kraw0.z; kh[3] = *(__half2*)&kraw0.w;
        kh[4] = *(__half2*)&kraw1.x; kh[5] = *(__half2*)&kraw1.y;
        kh[6] = *(__half2*)&kraw1.z; kh[7] = *(__half2*)&kraw1.w;

        bool qm = mask[(size_t)b*Np + nw*Wp + quar] != 0;

        float pw[4] = {0.f, 0.f, 0.f, 0.f};
        #pragma unroll
        for (int i = 0; i < 8; i++) {
            float2 kf = __half22float2(kh[i]);
            #pragma unroll
            for (int w = 0; w < 4; w++) {
                float q0 = qs[w][quar*16 + i*2];
                float q1 = qs[w][quar*16 + i*2 + 1];
                pw[w] += q0*kf.x + q1*kf.y;
            }
        }
        #pragma unroll
        for (int w = 0; w < 4; w++) {
            pw[w] += __shfl_xor_sync(0xffffffffu, pw[w], 1);
            pw[w] += __shfl_xor_sync(0xffffffffu, pw[w], 2);
        }
        float val = pw[quar]*scale + pb_s[quar][z];
        if (qm && km_s[z]) val = -3.402823466e38f;
        sd[quar][z] = val;
    }
    __syncthreads();

    if (t < 128) {
        int w = t >> 5, lane = t & 31;
        float v0 = sd[w][lane], v1 = sd[w][lane+32];
        float m = fmaxf(v0, v1);
        #pragma unroll
        for (int off = 16; off > 0; off >>= 1)
            m = fmaxf(m, __shfl_xor_sync(0xffffffffu, m, off));
        float e0 = __expf(v0 - m), e1 = __expf(v1 - m);
        float s = e0 + e1;
        #pragma unroll
        for (int off = 16; off > 0; off >>= 1)
            s += __shfl_xor_sync(0xffffffffu, s, off);
        float inv = 1.f / s;
        sd[w][lane]    = e0*inv;
        sd[w][lane+32] = e1*inv;
    }
    __syncthreads();

    {
        int g = t >> 6, d = t & 63;
        const __half* vbase = g_v16 + ((size_t)b*Np*Hp + h)*Dp + d;
        float a0 = 0.f, a1 = 0.f, a2 = 0.f, a3 = 0.f;
        #pragma unroll
        for (int c = 0; c < 4; c++) {
            float4 s0 = *(const float4*)&sd[0][g*16 + c*4];
            float4 s1 = *(const float4*)&sd[1][g*16 + c*4];
            float4 s2 = *(const float4*)&sd[2][g*16 + c*4];
            float4 s3 = *(const float4*)&sd[3][g*16 + c*4];
            float sv0[4] = {s0.x, s0.y, s0.z, s0.w};
            float sv1[4] = {s1.x, s1.y, s1.z, s1.w};
            float sv2[4] = {s2.x, s2.y, s2.z, s2.w};
            float sv3[4] = {s3.x, s3.y, s3.z, s3.w};
            #pragma unroll
            for (int j = 0; j < 4; j++) {
                int z = g*16 + c*4 + j;
                int row = sidx[z];
                float vv = __half2float(__ldg(vbase + (size_t)row*Hp*Dp));
                a0 += sv0[j] * vv;
                a1 += sv1[j] * vv;
                a2 += sv2[j] * vv;
                a3 += sv3[j] * vv;
            }
        }
        partial[g][0][d] = a0;
        partial[g][1][d] = a1;
        partial[g][2][d] = a2;
        partial[g][3][d] = a3;
    }
    __syncthreads();

    {
        int w = t >> 6, d = t & 63;
        float acc = partial[0][w][d] + partial[1][w][d]
                  + partial[2][w][d] + partial[3][w][d];
        g_attn16[((size_t)b*Np + nw*Wp + w)*(Hp*Dp) + h*Dp + d] = __float2half(acc);
    }
}

// ---------------------------------------------------------------------------
extern "C" void kernel_launch(void* const* d_in, const int* in_sizes, int n_in,
                              void* d_out, int out_size)
{
    const float* x            = (const float*)d_in[0];
    const unsigned char* mask = (const unsigned char*)d_in[1];
    const float* pos_bias     = (const float*)d_in[2];
    const float* pareto       = (const float*)d_in[3];
    const float* Wqkv         = (const float*)d_in[4];
    const float* bqkv         = (const float*)d_in[5];
    const float* Wo           = (const float*)d_in[6];
    const float* bo           = (const float*)d_in[7];
    float* out                = (float*)d_out;

    (void)in_sizes; (void)n_in; (void)out_size;

    static cudaStream_t s2 = nullptr;
    static cudaEvent_t evFork = nullptr, evPerm = nullptr, evJoin = nullptr, evWo = nullptr;
    if (s2 == nullptr) {
        cudaStreamCreateWithFlags(&s2, cudaStreamNonBlocking);
        cudaEventCreateWithFlags(&evFork, cudaEventDisableTiming);
        cudaEventCreateWithFlags(&evPerm, cudaEventDisableTiming);
        cudaEventCreateWithFlags(&evJoin, cudaEventDisableTiming);
        cudaEventCreateWithFlags(&evWo, cudaEventDisableTiming);
        cudaFuncSetAttribute(gemm_f16_kernel<0>,
            cudaFuncAttributeMaxDynamicSharedMemorySize, GEMM_SMEM);
        cudaFuncSetAttribute(gemm_f16_kernel<1>,
            cudaFuncAttributeMaxDynamicSharedMemorySize, GEMM_SMEM);
    }

    // Side stream: producers for gemm0, select (evJoin), then Wo transpose.
    cudaEventRecord(evFork, 0);
    cudaStreamWaitEvent(s2, evFork, 0);
    permW_kernel<<<dim3(48,16), dim3(32,32), 0, s2>>>(Wqkv, bqkv);
    convX_kernel<<<(Bp*Np*Cp/4)/256, 256, 0, s2>>>(x);
    cudaEventRecord(evPerm, s2);
    select_kernel<<<Bp*Hp*NWp, 256, 0, s2>>>(pareto, mask);
    cudaEventRecord(evJoin, s2);
    convWo_kernel<<<dim3(16,16), dim3(32,32), 0, s2>>>(Wo);
    cudaEventRecord(evWo, s2);

    // QKV GEMM (fp16 tensor cores, fp16 q/k/v epilogue).
    cudaStreamWaitEvent(0, evPerm, 0);
    {
        dim3 grid(3*Hp*Dp/128, Bp*Np/128);   // 12 x 64
        gemm_f16_kernel<0><<<grid, 256, GEMM_SMEM>>>(nullptr, nullptr, 3*Hp*Dp);
    }

    // Attention (needs q/k/v + g_idx).
    cudaStreamWaitEvent(0, evJoin, 0);
    attn_kernel<<<Bp*Hp*NWp, 256>>>(pos_bias, mask);

    // Output projection (needs g_attn16 + g_Wo16).
    cudaStreamWaitEvent(0, evWo, 0);
    {
        dim3 grid(Cp/128, Bp*Np/128);        // 4 x 64
        gemm_f16_kernel<1><<<grid, 256, GEMM_SMEM>>>(bo, out, Cp);
    }
}

// round 16
// speedup vs baseline: 1.4484x; 1.0703x over previous
#include <cuda_runtime.h>
#include <cuda_fp16.h>
#include <math.h>
#include <stdint.h>

// Problem constants
#define Bp 4
#define Np 2048
#define Cp 512
#define Hp 8
#define Dp 64
#define Wp 4
#define NWp 512
#define KEEP 64

// Scratch (device globals; no allocation allowed)
__device__ __half g_q16[Bp*Np*Hp*Dp];      // [B,N,H,D] fp16
__device__ __half g_k16[Bp*Np*Hp*Dp];
__device__ __half g_v16[Bp*Np*Hp*Dp];
__device__ __half g_attn16[Bp*Np*Hp*Dp];   // [B,N,H*D], fp16 (gemm1 A)
__device__ int    g_idx[Bp*Hp*NWp*KEEP];   // [B,H,NW,64]
__device__ __half g_Wperm16[3*Hp*Dp*Cp];   // Wqkv^T permuted: [u=(s,h,d)][k]
__device__ float  g_bperm[3*Hp*Dp];
__device__ __half g_x16[Bp*Np*Cp];         // x, fp16 (K-major)
__device__ __half g_Wo16[Cp*Cp];           // Wo^T: [n][k], fp16

// ---------------------------------------------------------------------------
// Helpers
// ---------------------------------------------------------------------------
__device__ __forceinline__ void mma_f16(float4& d,
    unsigned a0, unsigned a1, unsigned a2, unsigned a3,
    unsigned b0, unsigned b1)
{
    asm volatile(
        "mma.sync.aligned.m16n8k16.row.col.f32.f16.f16.f32 "
        "{%0,%1,%2,%3}, {%4,%5,%6,%7}, {%8,%9}, {%0,%1,%2,%3};\n"
        : "+f"(d.x), "+f"(d.y), "+f"(d.z), "+f"(d.w)
        : "r"(a0), "r"(a1), "r"(a2), "r"(a3), "r"(b0), "r"(b1));
}

__device__ __forceinline__ uint32_t smem_u32(const void* p) {
    uint32_t a;
    asm("{ .reg .u64 t; cvta.to.shared.u64 t, %1; cvt.u32.u64 %0, t; }"
        : "=r"(a) : "l"(p));
    return a;
}

__device__ __forceinline__ void cp16s(uint32_t dst_smem, const void* src) {
    asm volatile("cp.async.cg.shared.global [%0], [%1], 16;"
                 :: "r"(dst_smem), "l"(src));
}
#define CP_COMMIT() asm volatile("cp.async.commit_group;")
#define CP_WAIT0()  asm volatile("cp.async.wait_group 0;")

// ---------------------------------------------------------------------------
// Producers (side stream, hidden): fp16 conversions + weight transposes.
// ---------------------------------------------------------------------------
__global__ __launch_bounds__(256) void convX_kernel(const float* __restrict__ x)
{
    int i = blockIdx.x*256 + threadIdx.x;
    float4 v = *(const float4*)(x + (size_t)i*4);
    __half2 h0 = __floats2half2_rn(v.x, v.y);
    __half2 h1 = __floats2half2_rn(v.z, v.w);
    uint2 o = make_uint2(*(unsigned*)&h0, *(unsigned*)&h1);
    *(uint2*)(g_x16 + (size_t)i*4) = o;
}

__global__ void permW_kernel(const float* __restrict__ Wqkv,
                             const float* __restrict__ bqkv)
{
    __shared__ float tile[32][33];
    int tx = threadIdx.x, ty = threadIdx.y;
    int c = blockIdx.x*32 + tx;     // 0..1535
    int k = blockIdx.y*32 + ty;     // 0..511
    tile[ty][tx] = Wqkv[(size_t)k*1536 + c];
    __syncthreads();
    int c2 = blockIdx.x*32 + ty;
    int hd = c2 / 3, s = c2 - hd*3;
    int u = s*512 + hd;
    int k2 = blockIdx.y*32 + tx;
    g_Wperm16[(size_t)u*512 + k2] = __float2half(tile[tx][ty]);
    if (blockIdx.y == 0 && ty == 0) {
        int cc = blockIdx.x*32 + tx;
        int hd2 = cc / 3, s2 = cc - hd2*3;
        g_bperm[s2*512 + hd2] = bqkv[cc];
    }
}

__global__ void convWo_kernel(const float* __restrict__ Wo)
{
    __shared__ float tile[32][33];
    int tx = threadIdx.x, ty = threadIdx.y;
    int n = blockIdx.x*32 + tx;
    int k = blockIdx.y*32 + ty;
    tile[ty][tx] = Wo[(size_t)k*512 + n];
    __syncthreads();
    g_Wo16[(size_t)(blockIdx.x*32 + ty)*512 + blockIdx.y*32 + tx]
        = __float2half(tile[tx][ty]);
}

// ---------------------------------------------------------------------------
// fp16 tensor-core GEMM: C[M,Nn] = A[M,512] @ B^T (B stored [Nn][512]).
// ---------------------------------------------------------------------------
#define AS_H 40
#define MAT_HALFS (128*AS_H)
#define STAGE_HALFS (2*MAT_HALFS)
#define STAGE_BYTES (STAGE_HALFS*2)   // 20480 B
#define GEMM_SMEM (2*STAGE_BYTES)     // 40960 B

template<int EPI>
__global__ __launch_bounds__(256, 2) void gemm_f16_kernel(
    const float* __restrict__ biasIn,
    float* __restrict__ Cout,
    int Nn)
{
    extern __shared__ __half smh[];
    uint32_t smem_base = smem_u32(smh);

    const __half* A    = (EPI == 0) ? (const __half*)g_x16    : (const __half*)g_attn16;
    const __half* Bw   = (EPI == 0) ? (const __half*)g_Wperm16 : (const __half*)g_Wo16;
    const float*  bias = (EPI == 0) ? (const float*)g_bperm   : biasIn;

    int tid = threadIdx.x;
    int bx = blockIdx.x, by = blockIdx.y;
    int warp = tid >> 5, lane = tid & 31;
    int wm = warp & 1, wn = warp >> 1;
    int gid = lane >> 2, tig = lane & 3;

    float4 acc[4][4];
    #pragma unroll
    for (int i = 0; i < 4; i++)
        #pragma unroll
        for (int j = 0; j < 4; j++) acc[i][j] = make_float4(0.f,0.f,0.f,0.f);

    auto load_tile = [&](int st, int kt) {
        #pragma unroll
        for (int i = 0; i < 2; i++) {
            int f = tid + i*256;
            int row = f >> 2, c16 = f & 3;
            uint32_t dA = smem_base + st*STAGE_BYTES + row*80 + c16*16;
            uint32_t dB = dA + MAT_HALFS*2;
            cp16s(dA, A  + (size_t)(by*128 + row)*512 + kt*32 + c16*8);
            cp16s(dB, Bw + (size_t)(bx*128 + row)*512 + kt*32 + c16*8);
        }
        CP_COMMIT();
    };

    load_tile(0, 0);
    CP_WAIT0();
    __syncthreads();

    for (int kt = 0; kt < 16; kt++) {
        if (kt + 1 < 16) load_tile((kt+1)&1, kt+1);

        const __half* Asc = smh + (kt&1)*STAGE_HALFS;
        const __half* Bsc = Asc + MAT_HALFS;
        #pragma unroll
        for (int ks = 0; ks < 2; ks++) {
            int k0 = ks*16;
            unsigned af[4][4], bf[4][2];
            #pragma unroll
            for (int i = 0; i < 4; i++) {
                int r = wm*64 + i*16 + gid;
                af[i][0] = *(const unsigned*)&Asc[ r    *AS_H + k0 + tig*2];
                af[i][1] = *(const unsigned*)&Asc[(r+8)*AS_H + k0 + tig*2];
                af[i][2] = *(const unsigned*)&Asc[ r    *AS_H + k0 + tig*2 + 8];
                af[i][3] = *(const unsigned*)&Asc[(r+8)*AS_H + k0 + tig*2 + 8];
            }
            #pragma unroll
            for (int j = 0; j < 4; j++) {
                int c = wn*32 + j*8 + gid;
                bf[j][0] = *(const unsigned*)&Bsc[c*AS_H + k0 + tig*2];
                bf[j][1] = *(const unsigned*)&Bsc[c*AS_H + k0 + tig*2 + 8];
            }
            #pragma unroll
            for (int i = 0; i < 4; i++)
                #pragma unroll
                for (int j = 0; j < 4; j++)
                    mma_f16(acc[i][j], af[i][0], af[i][1], af[i][2], af[i][3],
                            bf[j][0], bf[j][1]);
        }

        if (kt + 1 < 16) CP_WAIT0();
        __syncthreads();
    }

    if (EPI == 0) {
        int sq = bx >> 2;
        __half* dst = (sq == 0) ? g_q16 : (sq == 1) ? g_k16 : g_v16;
        int colBase = (bx & 3)*128;
        #pragma unroll
        for (int i = 0; i < 4; i++) {
            int m0 = by*128 + wm*64 + i*16 + gid;
            #pragma unroll
            for (int j = 0; j < 4; j++) {
                int cl = wn*32 + j*8 + tig*2;
                float bz0 = bias[bx*128 + cl];
                float bz1 = bias[bx*128 + cl + 1];
                float4 d = acc[i][j];
                __half2 h0 = __floats2half2_rn(d.x + bz0, d.y + bz1);
                __half2 h1 = __floats2half2_rn(d.z + bz0, d.w + bz1);
                *(__half2*)(dst + (size_t)m0*512 + colBase + cl)     = h0;
                *(__half2*)(dst + (size_t)(m0+8)*512 + colBase + cl) = h1;
            }
        }
    } else {
        #pragma unroll
        for (int i = 0; i < 4; i++) {
            int m0 = by*128 + wm*64 + i*16 + gid;
            #pragma unroll
            for (int j = 0; j < 4; j++) {
                int cl = wn*32 + j*8 + tig*2;
                float bz0 = bias[bx*128 + cl];
                float bz1 = bias[bx*128 + cl + 1];
                float4 d = acc[i][j];
                float2 o0 = make_float2(d.x + bz0, d.y + bz1);
                float2 o1 = make_float2(d.z + bz0, d.w + bz1);
                *(float2*)(Cout + (size_t)m0*Nn + bx*128 + cl)     = o0;
                *(float2*)(Cout + (size_t)(m0+8)*Nn + bx*128 + cl) = o1;
            }
        }
    }
}

// ---------------------------------------------------------------------------
// Block-wide inclusive scan (256 threads) via warp shuffles.
// ---------------------------------------------------------------------------
__device__ __forceinline__ unsigned blockScanIncl(unsigned v, unsigned* warpSums, int t)
{
    int lane = t & 31, wid = t >> 5;
    #pragma unroll
    for (int off = 1; off < 32; off <<= 1) {
        unsigned n = __shfl_up_sync(0xffffffffu, v, off);
        if (lane >= off) v += n;
    }
    if (lane == 31) warpSums[wid] = v;
    __syncthreads();
    if (wid == 0) {
        unsigned s = (lane < 8) ? warpSums[lane] : 0u;
        #pragma unroll
        for (int off = 1; off < 8; off <<= 1) {
            unsigned n = __shfl_up_sync(0xffffffffu, s, off);
            if (lane >= off) s += n;
        }
        if (lane < 8) warpSums[lane] = s;
    }
    __syncthreads();
    if (wid > 0) v += warpSums[wid - 1];
    return v;
}

template<int NB>
__device__ __forceinline__ void findThresholdBin(
    const unsigned* hist, unsigned r, unsigned* warpSums, unsigned* sOut, int t)
{
    const int PER = NB / 256;
    unsigned loc[PER];
    unsigned s = 0;
    #pragma unroll
    for (int i = 0; i < PER; i++) { loc[i] = hist[t*PER + i]; s += loc[i]; }
    unsigned incl = blockScanIncl(s, warpSums, t);
    unsigned excl = incl - s;
    if (excl < r && r <= incl) {
        unsigned cum = excl;
        #pragma unroll
        for (int i = 0; i < PER; i++) {
            if (cum + loc[i] >= r) { sOut[0] = t*PER + i; sOut[1] = cum; break; }
            cum += loc[i];
        }
    }
    __syncthreads();
}

// ---------------------------------------------------------------------------
// Selection: pass-1 11-bit radix + exact rank-count on candidates.
// ---------------------------------------------------------------------------
__global__ __launch_bounds__(256) void select_kernel(
    const float* __restrict__ pareto,
    const unsigned char* __restrict__ mask)
{
    __shared__ unsigned hist[2048];
    __shared__ unsigned cand[2048];
    __shared__ unsigned warpSums[8];
    __shared__ unsigned sOut[2];
    __shared__ unsigned sCnt;
    __shared__ unsigned sT, sRR;

    int p = blockIdx.x;
    int nw = p & (NWp-1);
    int b  = p / (Hp*NWp);
    int t  = threadIdx.x;

    const float* prow = pareto + (size_t)p * Np;
    const unsigned char* mrow = mask + (size_t)b * Np;

    unsigned long long mbits = *(const unsigned long long*)(mrow + t*8);
    unsigned key[8];
    #pragma unroll
    for (int v = 0; v < 2; v++) {
        float4 nz = *(const float4*)(prow + t*8 + v*4);
        float noise[4] = {nz.x, nz.y, nz.z, nz.w};
        int ag = nw - (t*2 + v); if (ag < 0) ag = -ag;
        float gridv = (float)ag;
        #pragma unroll
        for (int i = 0; i < 4; i++) {
            float val = gridv - noise[i];
            if ((mbits >> ((v*4 + i)*8)) & 0xFFull) val = 3.402823466e38f;
            unsigned ub = __float_as_uint(val);
            ub ^= ((unsigned)((int)ub >> 31)) | 0x80000000u;
            key[v*4 + i] = ub;
        }
    }

    #pragma unroll
    for (int i = 0; i < 8; i++) hist[t*8 + i] = 0;
    __syncthreads();
    #pragma unroll
    for (int i = 0; i < 8; i++)
        atomicAdd(&hist[key[i] >> 21], 1u);
    __syncthreads();

    unsigned r = 64;
    findThresholdBin<2048>(hist, r, warpSums, sOut, t);
    unsigned bin1 = sOut[0];
    r -= sOut[1];
    __syncthreads();

    if (t == 0) sCnt = 0;
    __syncthreads();
    #pragma unroll
    for (int i = 0; i < 8; i++)
        if ((key[i] >> 21) == bin1)
            cand[atomicAdd(&sCnt, 1u)] = key[i];
    __syncthreads();
    unsigned E = sCnt;

    if (E > 256) {
        #pragma unroll
        for (int i = 0; i < 8; i++) hist[t*8 + i] = 0;
        unsigned kk[8]; int n = 0;
        for (unsigned j = t; j < E; j += 256) kk[n++] = cand[j];
        __syncthreads();
        for (int i = 0; i < n; i++)
            atomicAdd(&hist[(kk[i] >> 10) & 0x7FFu], 1u);
        __syncthreads();
        findThresholdBin<2048>(hist, r, warpSums, sOut, t);
        unsigned bin2 = sOut[0];
        r -= sOut[1];
        __syncthreads();
        if (t == 0) sCnt = 0;
        __syncthreads();
        for (int i = 0; i < n; i++)
            if (((kk[i] >> 10) & 0x7FFu) == bin2)
                cand[atomicAdd(&sCnt, 1u)] = kk[i];
        __syncthreads();
        E = sCnt;
    }

    for (unsigned e = t; e < E; e += 256) {
        unsigned ke = cand[e];
        unsigned less = 0, eq = 0;
        for (unsigned i = 0; i < E; i++) {
            unsigned ki = cand[i];
            less += (ki < ke);
            eq   += (ki == ke);
        }
        if (less < r && r <= less + eq) { sT = ke; sRR = r - less; }
    }
    __syncthreads();
    unsigned T = sT;
    unsigned rr = sRR;

    unsigned lessC = 0, eqC = 0;
    #pragma unroll
    for (int i = 0; i < 8; i++) {
        lessC += (key[i] < T);
        eqC   += (key[i] == T);
    }
    unsigned packed = lessC | (eqC << 16);
    unsigned incl = blockScanIncl(packed, warpSums, t);
    unsigned lb = (incl & 0xFFFFu) - lessC;
    unsigned eb = (incl >> 16)     - eqC;

    int* oidx = g_idx + (size_t)p * KEEP;
    #pragma unroll
    for (int i = 0; i < 8; i++) {
        int j = t*8 + i;
        unsigned k = key[i];
        if (k < T) {
            oidx[lb + min(eb, rr)] = j;
            lb++;
        } else if (k == T) {
            if (eb < rr) oidx[lb + eb] = j;
            eb++;
        }
    }
}

// ---------------------------------------------------------------------------
// Attention: q/k/v fp16; AV remapped so each warp covers a full 128B V row
// per wavefront (8 z-groups of 8, __half2 per thread).
// ---------------------------------------------------------------------------
#define PADR 68
__global__ __launch_bounds__(256) void attn_kernel(
    const float* __restrict__ pos_bias,
    const unsigned char* __restrict__ mask)
{
    __shared__ int   sidx[KEEP];
    __shared__ float qs[Wp][PADR];
    __shared__ float sd[Wp][PADR];
    __shared__ float pb_s[Wp][PADR];
    __shared__ unsigned char km_s[KEEP];
    __shared__ float partial[8][Wp][Dp];

    int p  = blockIdx.x;
    int nw = p & (NWp-1);
    int bh = p >> 9;
    int h  = bh & (Hp-1);
    int b  = bh >> 3;
    int t  = threadIdx.x;

    if (t < KEEP) sidx[t] = g_idx[(size_t)p * KEEP + t];
    {
        int w = t >> 6, d = t & 63;
        qs[w][d] = __half2float(
            g_q16[((size_t)(b*Np + nw*Wp + w)*Hp + h)*Dp + d]);
    }
    __syncthreads();

    {
        int w = t >> 6, z = t & 63;
        int key = sidx[z];
        pb_s[w][z] = __ldg(pos_bias + ((size_t)h*Np + nw*Wp + w)*Np + key);
        if (t < KEEP) km_s[t] = mask[(size_t)b*Np + sidx[t]];
    }
    __syncthreads();

    const float scale = 0.125f;
    {
        int z = t >> 2, quar = t & 3;
        int row = sidx[z];
        const __half* kp = g_k16 + ((size_t)(b*Np + row)*Hp + h)*Dp + quar*16;
        uint4 kraw0 = __ldg((const uint4*)kp);
        uint4 kraw1 = __ldg((const uint4*)(kp + 8));
        __half2 kh[8];
        kh[0] = *(__half2*)&kraw0.x; kh[1] = *(__half2*)&kraw0.y;
        kh[2] = *(__half2*)&kraw0.z; kh[3] = *(__half2*)&kraw0.w;
        kh[4] = *(__half2*)&kraw1.x; kh[5] = *(__half2*)&kraw1.y;
        kh[6] = *(__half2*)&kraw1.z; kh[7] = *(__half2*)&kraw1.w;

        bool qm = mask[(size_t)b*Np + nw*Wp + quar] != 0;

        float pw[4] = {0.f, 0.f, 0.f, 0.f};
        #pragma unroll
        for (int i = 0; i < 8; i++) {
            float2 kf = __half22float2(kh[i]);
            #pragma unroll
            for (int w = 0; w < 4; w++) {
                float q0 = qs[w][quar*16 + i*2];
                float q1 = qs[w][quar*16 + i*2 + 1];
                pw[w] += q0*kf.x + q1*kf.y;
            }
        }
        #pragma unroll
        for (int w = 0; w < 4; w++) {
            pw[w] += __shfl_xor_sync(0xffffffffu, pw[w], 1);
            pw[w] += __shfl_xor_sync(0xffffffffu, pw[w], 2);
        }
        float val = pw[quar]*scale + pb_s[quar][z];
        if (qm && km_s[z]) val = -3.402823466e38f;
        sd[quar][z] = val;
    }
    __syncthreads();

    if (t < 128) {
        int w = t >> 5, lane = t & 31;
        float v0 = sd[w][lane], v1 = sd[w][lane+32];
        float m = fmaxf(v0, v1);
        #pragma unroll
        for (int off = 16; off > 0; off >>= 1)
            m = fmaxf(m, __shfl_xor_sync(0xffffffffu, m, off));
        float e0 = __expf(v0 - m), e1 = __expf(v1 - m);
        float s = e0 + e1;
        #pragma unroll
        for (int off = 16; off > 0; off >>= 1)
            s += __shfl_xor_sync(0xffffffffu, s, off);
        float inv = 1.f / s;
        sd[w][lane]    = e0*inv;
        sd[w][lane+32] = e1*inv;
    }
    __syncthreads();

    // AV phase 1: warp g (0..7) owns z in [g*8, g*8+8); thread handles
    // d = {2*lane, 2*lane+1}. One 128B wavefront per V row per warp.
    {
        int g = t >> 5, lane = t & 31;
        const __half* vbase = g_v16 + ((size_t)b*Np*Hp + h)*Dp + 2*lane;
        // preload sd slice (warp-uniform broadcast reads)
        float sdv[4][8];
        #pragma unroll
        for (int w = 0; w < 4; w++) {
            float4 lo = *(const float4*)&sd[w][g*8];
            float4 hi = *(const float4*)&sd[w][g*8 + 4];
            sdv[w][0]=lo.x; sdv[w][1]=lo.y; sdv[w][2]=lo.z; sdv[w][3]=lo.w;
            sdv[w][4]=hi.x; sdv[w][5]=hi.y; sdv[w][6]=hi.z; sdv[w][7]=hi.w;
        }
        float a0[4], a1[4];
        #pragma unroll
        for (int w = 0; w < 4; w++) { a0[w] = 0.f; a1[w] = 0.f; }
        #pragma unroll
        for (int zi = 0; zi < 8; zi++) {
            int row = sidx[g*8 + zi];
            __half2 vv = __ldg((const __half2*)(vbase + (size_t)row*Hp*Dp));
            float2 vf = __half22float2(vv);
            #pragma unroll
            for (int w = 0; w < 4; w++) {
                a0[w] += sdv[w][zi] * vf.x;
                a1[w] += sdv[w][zi] * vf.y;
            }
        }
        #pragma unroll
        for (int w = 0; w < 4; w++)
            *(float2*)&partial[g][w][2*lane] = make_float2(a0[w], a1[w]);
    }
    __syncthreads();

    // AV phase 2: reduce 8 partials, write out
    {
        int w = t >> 6, d = t & 63;
        float acc = 0.f;
        #pragma unroll
        for (int g = 0; g < 8; g++) acc += partial[g][w][d];
        g_attn16[((size_t)b*Np + nw*Wp + w)*(Hp*Dp) + h*Dp + d] = __float2half(acc);
    }
}

// ---------------------------------------------------------------------------
extern "C" void kernel_launch(void* const* d_in, const int* in_sizes, int n_in,
                              void* d_out, int out_size)
{
    const float* x            = (const float*)d_in[0];
    const unsigned char* mask = (const unsigned char*)d_in[1];
    const float* pos_bias     = (const float*)d_in[2];
    const float* pareto       = (const float*)d_in[3];
    const float* Wqkv         = (const float*)d_in[4];
    const float* bqkv         = (const float*)d_in[5];
    const float* Wo           = (const float*)d_in[6];
    const float* bo           = (const float*)d_in[7];
    float* out                = (float*)d_out;

    (void)in_sizes; (void)n_in; (void)out_size;

    static cudaStream_t s2 = nullptr;
    static cudaEvent_t evFork = nullptr, evPerm = nullptr, evJoin = nullptr, evWo = nullptr;
    if (s2 == nullptr) {
        cudaStreamCreateWithFlags(&s2, cudaStreamNonBlocking);
        cudaEventCreateWithFlags(&evFork, cudaEventDisableTiming);
        cudaEventCreateWithFlags(&evPerm, cudaEventDisableTiming);
        cudaEventCreateWithFlags(&evJoin, cudaEventDisableTiming);
        cudaEventCreateWithFlags(&evWo, cudaEventDisableTiming);
        cudaFuncSetAttribute(gemm_f16_kernel<0>,
            cudaFuncAttributeMaxDynamicSharedMemorySize, GEMM_SMEM);
        cudaFuncSetAttribute(gemm_f16_kernel<1>,
            cudaFuncAttributeMaxDynamicSharedMemorySize, GEMM_SMEM);
    }

    // Side stream: producers for gemm0, select (evJoin), then Wo transpose.
    cudaEventRecord(evFork, 0);
    cudaStreamWaitEvent(s2, evFork, 0);
    permW_kernel<<<dim3(48,16), dim3(32,32), 0, s2>>>(Wqkv, bqkv);
    convX_kernel<<<(Bp*Np*Cp/4)/256, 256, 0, s2>>>(x);
    cudaEventRecord(evPerm, s2);
    select_kernel<<<Bp*Hp*NWp, 256, 0, s2>>>(pareto, mask);
    cudaEventRecord(evJoin, s2);
    convWo_kernel<<<dim3(16,16), dim3(32,32), 0, s2>>>(Wo);
    cudaEventRecord(evWo, s2);

    // QKV GEMM (fp16 tensor cores, fp16 q/k/v epilogue).
    cudaStreamWaitEvent(0, evPerm, 0);
    {
        dim3 grid(3*Hp*Dp/128, Bp*Np/128);   // 12 x 64
        gemm_f16_kernel<0><<<grid, 256, GEMM_SMEM>>>(nullptr, nullptr, 3*Hp*Dp);
    }

    // Attention (needs q/k/v + g_idx).
    cudaStreamWaitEvent(0, evJoin, 0);
    attn_kernel<<<Bp*Hp*NWp, 256>>>(pos_bias, mask);

    // Output projection (needs g_attn16 + g_Wo16).
    cudaStreamWaitEvent(0, evWo, 0);
    {
        dim3 grid(Cp/128, Bp*Np/128);        // 4 x 64
        gemm_f16_kernel<1><<<grid, 256, GEMM_SMEM>>>(bo, out, Cp);
    }
}

// round 17
// speedup vs baseline: 1.5071x; 1.0405x over previous
#include <cuda_runtime.h>
#include <cuda_fp16.h>
#include <math.h>
#include <stdint.h>

// Problem constants
#define Bp 4
#define Np 2048
#define Cp 512
#define Hp 8
#define Dp 64
#define Wp 4
#define NWp 512
#define KEEP 64

// Scratch (device globals; no allocation allowed)
__device__ __half g_q16[Bp*Np*Hp*Dp];      // [B,N,H,D] fp16
__device__ __half g_k16[Bp*Np*Hp*Dp];
__device__ __half g_v16[Bp*Np*Hp*Dp];
__device__ __half g_attn16[Bp*Np*Hp*Dp];   // [B,N,H*D], fp16 (gemm1 A)
__device__ int    g_idx[Bp*Hp*NWp*KEEP];   // [B,H,NW,64]
__device__ __half g_Wperm16[3*Hp*Dp*Cp];   // Wqkv^T permuted: [u=(s,h,d)][k]
__device__ float  g_bperm[3*Hp*Dp];
__device__ __half g_x16[Bp*Np*Cp];         // x, fp16 (K-major)
__device__ __half g_Wo16[Cp*Cp];           // Wo^T: [n][k], fp16

// ---------------------------------------------------------------------------
// Helpers
// ---------------------------------------------------------------------------
__device__ __forceinline__ void mma_f16(float4& d,
    unsigned a0, unsigned a1, unsigned a2, unsigned a3,
    unsigned b0, unsigned b1)
{
    asm volatile(
        "mma.sync.aligned.m16n8k16.row.col.f32.f16.f16.f32 "
        "{%0,%1,%2,%3}, {%4,%5,%6,%7}, {%8,%9}, {%0,%1,%2,%3};\n"
        : "+f"(d.x), "+f"(d.y), "+f"(d.z), "+f"(d.w)
        : "r"(a0), "r"(a1), "r"(a2), "r"(a3), "r"(b0), "r"(b1));
}

__device__ __forceinline__ void ldsm_x4(unsigned& r0, unsigned& r1,
                                        unsigned& r2, unsigned& r3, uint32_t addr)
{
    asm volatile("ldmatrix.sync.aligned.m8n8.x4.shared.b16 {%0,%1,%2,%3}, [%4];"
                 : "=r"(r0), "=r"(r1), "=r"(r2), "=r"(r3) : "r"(addr));
}
__device__ __forceinline__ void ldsm_x2(unsigned& r0, unsigned& r1, uint32_t addr)
{
    asm volatile("ldmatrix.sync.aligned.m8n8.x2.shared.b16 {%0,%1}, [%2];"
                 : "=r"(r0), "=r"(r1) : "r"(addr));
}

__device__ __forceinline__ uint32_t smem_u32(const void* p) {
    uint32_t a;
    asm("{ .reg .u64 t; cvta.to.shared.u64 t, %1; cvt.u32.u64 %0, t; }"
        : "=r"(a) : "l"(p));
    return a;
}

__device__ __forceinline__ void cp16s(uint32_t dst_smem, const void* src) {
    asm volatile("cp.async.cg.shared.global [%0], [%1], 16;"
                 :: "r"(dst_smem), "l"(src));
}
#define CP_COMMIT() asm volatile("cp.async.commit_group;")
#define CP_WAIT0()  asm volatile("cp.async.wait_group 0;")

// ---------------------------------------------------------------------------
// Producers (side stream, hidden): fp16 conversions + weight transposes.
// ---------------------------------------------------------------------------
__global__ __launch_bounds__(256) void convX_kernel(const float* __restrict__ x)
{
    int i = blockIdx.x*256 + threadIdx.x;
    float4 v = *(const float4*)(x + (size_t)i*4);
    __half2 h0 = __floats2half2_rn(v.x, v.y);
    __half2 h1 = __floats2half2_rn(v.z, v.w);
    uint2 o = make_uint2(*(unsigned*)&h0, *(unsigned*)&h1);
    *(uint2*)(g_x16 + (size_t)i*4) = o;
}

__global__ void permW_kernel(const float* __restrict__ Wqkv,
                             const float* __restrict__ bqkv)
{
    __shared__ float tile[32][33];
    int tx = threadIdx.x, ty = threadIdx.y;
    int c = blockIdx.x*32 + tx;
    int k = blockIdx.y*32 + ty;
    tile[ty][tx] = Wqkv[(size_t)k*1536 + c];
    __syncthreads();
    int c2 = blockIdx.x*32 + ty;
    int hd = c2 / 3, s = c2 - hd*3;
    int u = s*512 + hd;
    int k2 = blockIdx.y*32 + tx;
    g_Wperm16[(size_t)u*512 + k2] = __float2half(tile[tx][ty]);
    if (blockIdx.y == 0 && ty == 0) {
        int cc = blockIdx.x*32 + tx;
        int hd2 = cc / 3, s2 = cc - hd2*3;
        g_bperm[s2*512 + hd2] = bqkv[cc];
    }
}

__global__ void convWo_kernel(const float* __restrict__ Wo)
{
    __shared__ float tile[32][33];
    int tx = threadIdx.x, ty = threadIdx.y;
    int n = blockIdx.x*32 + tx;
    int k = blockIdx.y*32 + ty;
    tile[ty][tx] = Wo[(size_t)k*512 + n];
    __syncthreads();
    g_Wo16[(size_t)(blockIdx.x*32 + ty)*512 + blockIdx.y*32 + tx]
        = __float2half(tile[tx][ty]);
}

// ---------------------------------------------------------------------------
// fp16 tensor-core GEMM with ldmatrix operand fetch.
// C[M,Nn] = A[M,512] @ B^T (B stored [Nn][512]).
// ---------------------------------------------------------------------------
#define AS_H 40
#define MAT_HALFS (128*AS_H)
#define STAGE_HALFS (2*MAT_HALFS)
#define STAGE_BYTES (STAGE_HALFS*2)   // 20480 B
#define GEMM_SMEM (2*STAGE_BYTES)     // 40960 B

template<int EPI>
__global__ __launch_bounds__(256, 2) void gemm_f16_kernel(
    const float* __restrict__ biasIn,
    float* __restrict__ Cout,
    int Nn)
{
    extern __shared__ __half smh[];
    uint32_t smem_base = smem_u32(smh);

    const __half* A    = (EPI == 0) ? (const __half*)g_x16    : (const __half*)g_attn16;
    const __half* Bw   = (EPI == 0) ? (const __half*)g_Wperm16 : (const __half*)g_Wo16;
    const float*  bias = (EPI == 0) ? (const float*)g_bperm   : biasIn;

    int tid = threadIdx.x;
    int bx = blockIdx.x, by = blockIdx.y;
    int warp = tid >> 5, lane = tid & 31;
    int wm = warp & 1, wn = warp >> 1;
    int gid = lane >> 2, tig = lane & 3;

    // ldmatrix per-lane base offsets (in halfs, within a stage's A / B region)
    // A .x4: row = wm*64 + i*16 + (lane&15); k-half = k0 + (lane>>4)*8
    uint32_t aOff = (uint32_t)((wm*64 + (lane & 15)) * AS_H + (lane >> 4)*8) * 2;
    // B .x2: n-row = wn*32 + j*8 + (lane&7); k-half = k0 + ((lane>>3)&1)*8
    uint32_t bOff = (uint32_t)((wn*32 + (lane & 7)) * AS_H + ((lane >> 3) & 1)*8) * 2;

    float4 acc[4][4];
    #pragma unroll
    for (int i = 0; i < 4; i++)
        #pragma unroll
        for (int j = 0; j < 4; j++) acc[i][j] = make_float4(0.f,0.f,0.f,0.f);

    auto load_tile = [&](int st, int kt) {
        #pragma unroll
        for (int i = 0; i < 2; i++) {
            int f = tid + i*256;
            int row = f >> 2, c16 = f & 3;
            uint32_t dA = smem_base + st*STAGE_BYTES + row*80 + c16*16;
            uint32_t dB = dA + MAT_HALFS*2;
            cp16s(dA, A  + (size_t)(by*128 + row)*512 + kt*32 + c16*8);
            cp16s(dB, Bw + (size_t)(bx*128 + row)*512 + kt*32 + c16*8);
        }
        CP_COMMIT();
    };

    load_tile(0, 0);
    CP_WAIT0();
    __syncthreads();

    for (int kt = 0; kt < 16; kt++) {
        if (kt + 1 < 16) load_tile((kt+1)&1, kt+1);

        uint32_t aBase = smem_base + (kt&1)*STAGE_BYTES + aOff;
        uint32_t bBase = smem_base + (kt&1)*STAGE_BYTES + MAT_HALFS*2 + bOff;
        #pragma unroll
        for (int ks = 0; ks < 2; ks++) {
            int k0b = ks*16*2;      // k0 in bytes
            unsigned af[4][4], bf[4][2];
            #pragma unroll
            for (int i = 0; i < 4; i++)
                ldsm_x4(af[i][0], af[i][1], af[i][2], af[i][3],
                        aBase + (uint32_t)(i*16*AS_H)*2 + k0b);
            #pragma unroll
            for (int j = 0; j < 4; j++)
                ldsm_x2(bf[j][0], bf[j][1],
                        bBase + (uint32_t)(j*8*AS_H)*2 + k0b);
            #pragma unroll
            for (int i = 0; i < 4; i++)
                #pragma unroll
                for (int j = 0; j < 4; j++)
                    mma_f16(acc[i][j], af[i][0], af[i][1], af[i][2], af[i][3],
                            bf[j][0], bf[j][1]);
        }

        if (kt + 1 < 16) CP_WAIT0();
        __syncthreads();
    }

    if (EPI == 0) {
        int sq = bx >> 2;
        __half* dst = (sq == 0) ? g_q16 : (sq == 1) ? g_k16 : g_v16;
        int colBase = (bx & 3)*128;
        #pragma unroll
        for (int i = 0; i < 4; i++) {
            int m0 = by*128 + wm*64 + i*16 + gid;
            #pragma unroll
            for (int j = 0; j < 4; j++) {
                int cl = wn*32 + j*8 + tig*2;
                float bz0 = bias[bx*128 + cl];
                float bz1 = bias[bx*128 + cl + 1];
                float4 d = acc[i][j];
                __half2 h0 = __floats2half2_rn(d.x + bz0, d.y + bz1);
                __half2 h1 = __floats2half2_rn(d.z + bz0, d.w + bz1);
                *(__half2*)(dst + (size_t)m0*512 + colBase + cl)     = h0;
                *(__half2*)(dst + (size_t)(m0+8)*512 + colBase + cl) = h1;
            }
        }
    } else {
        #pragma unroll
        for (int i = 0; i < 4; i++) {
            int m0 = by*128 + wm*64 + i*16 + gid;
            #pragma unroll
            for (int j = 0; j < 4; j++) {
                int cl = wn*32 + j*8 + tig*2;
                float bz0 = bias[bx*128 + cl];
                float bz1 = bias[bx*128 + cl + 1];
                float4 d = acc[i][j];
                float2 o0 = make_float2(d.x + bz0, d.y + bz1);
                float2 o1 = make_float2(d.z + bz0, d.w + bz1);
                *(float2*)(Cout + (size_t)m0*Nn + bx*128 + cl)     = o0;
                *(float2*)(Cout + (size_t)(m0+8)*Nn + bx*128 + cl) = o1;
            }
        }
    }
}

// ---------------------------------------------------------------------------
// Block-wide inclusive scan (256 threads) via warp shuffles.
// ---------------------------------------------------------------------------
__device__ __forceinline__ unsigned blockScanIncl(unsigned v, unsigned* warpSums, int t)
{
    int lane = t & 31, wid = t >> 5;
    #pragma unroll
    for (int off = 1; off < 32; off <<= 1) {
        unsigned n = __shfl_up_sync(0xffffffffu, v, off);
        if (lane >= off) v += n;
    }
    if (lane == 31) warpSums[wid] = v;
    __syncthreads();
    if (wid == 0) {
        unsigned s = (lane < 8) ? warpSums[lane] : 0u;
        #pragma unroll
        for (int off = 1; off < 8; off <<= 1) {
            unsigned n = __shfl_up_sync(0xffffffffu, s, off);
            if (lane >= off) s += n;
        }
        if (lane < 8) warpSums[lane] = s;
    }
    __syncthreads();
    if (wid > 0) v += warpSums[wid - 1];
    return v;
}

template<int NB>
__device__ __forceinline__ void findThresholdBin(
    const unsigned* hist, unsigned r, unsigned* warpSums, unsigned* sOut, int t)
{
    const int PER = NB / 256;
    unsigned loc[PER];
    unsigned s = 0;
    #pragma unroll
    for (int i = 0; i < PER; i++) { loc[i] = hist[t*PER + i]; s += loc[i]; }
    unsigned incl = blockScanIncl(s, warpSums, t);
    unsigned excl = incl - s;
    if (excl < r && r <= incl) {
        unsigned cum = excl;
        #pragma unroll
        for (int i = 0; i < PER; i++) {
            if (cum + loc[i] >= r) { sOut[0] = t*PER + i; sOut[1] = cum; break; }
            cum += loc[i];
        }
    }
    __syncthreads();
}

// ---------------------------------------------------------------------------
// Selection: pass-1 11-bit radix + exact rank-count on candidates.
// ---------------------------------------------------------------------------
__global__ __launch_bounds__(256) void select_kernel(
    const float* __restrict__ pareto,
    const unsigned char* __restrict__ mask)
{
    __shared__ unsigned hist[2048];
    __shared__ unsigned cand[2048];
    __shared__ unsigned warpSums[8];
    __shared__ unsigned sOut[2];
    __shared__ unsigned sCnt;
    __shared__ unsigned sT, sRR;

    int p = blockIdx.x;
    int nw = p & (NWp-1);
    int b  = p / (Hp*NWp);
    int t  = threadIdx.x;

    const float* prow = pareto + (size_t)p * Np;
    const unsigned char* mrow = mask + (size_t)b * Np;

    unsigned long long mbits = *(const unsigned long long*)(mrow + t*8);
    unsigned key[8];
    #pragma unroll
    for (int v = 0; v < 2; v++) {
        float4 nz = *(const float4*)(prow + t*8 + v*4);
        float noise[4] = {nz.x, nz.y, nz.z, nz.w};
        int ag = nw - (t*2 + v); if (ag < 0) ag = -ag;
        float gridv = (float)ag;
        #pragma unroll
        for (int i = 0; i < 4; i++) {
            float val = gridv - noise[i];
            if ((mbits >> ((v*4 + i)*8)) & 0xFFull) val = 3.402823466e38f;
            unsigned ub = __float_as_uint(val);
            ub ^= ((unsigned)((int)ub >> 31)) | 0x80000000u;
            key[v*4 + i] = ub;
        }
    }

    #pragma unroll
    for (int i = 0; i < 8; i++) hist[t*8 + i] = 0;
    __syncthreads();
    #pragma unroll
    for (int i = 0; i < 8; i++)
        atomicAdd(&hist[key[i] >> 21], 1u);
    __syncthreads();

    unsigned r = 64;
    findThresholdBin<2048>(hist, r, warpSums, sOut, t);
    unsigned bin1 = sOut[0];
    r -= sOut[1];
    __syncthreads();

    if (t == 0) sCnt = 0;
    __syncthreads();
    #pragma unroll
    for (int i = 0; i < 8; i++)
        if ((key[i] >> 21) == bin1)
            cand[atomicAdd(&sCnt, 1u)] = key[i];
    __syncthreads();
    unsigned E = sCnt;

    if (E > 256) {
        #pragma unroll
        for (int i = 0; i < 8; i++) hist[t*8 + i] = 0;
        unsigned kk[8]; int n = 0;
        for (unsigned j = t; j < E; j += 256) kk[n++] = cand[j];
        __syncthreads();
        for (int i = 0; i < n; i++)
            atomicAdd(&hist[(kk[i] >> 10) & 0x7FFu], 1u);
        __syncthreads();
        findThresholdBin<2048>(hist, r, warpSums, sOut, t);
        unsigned bin2 = sOut[0];
        r -= sOut[1];
        __syncthreads();
        if (t == 0) sCnt = 0;
        __syncthreads();
        for (int i = 0; i < n; i++)
            if (((kk[i] >> 10) & 0x7FFu) == bin2)
                cand[atomicAdd(&sCnt, 1u)] = kk[i];
        __syncthreads();
        E = sCnt;
    }

    for (unsigned e = t; e < E; e += 256) {
        unsigned ke = cand[e];
        unsigned less = 0, eq = 0;
        for (unsigned i = 0; i < E; i++) {
            unsigned ki = cand[i];
            less += (ki < ke);
            eq   += (ki == ke);
        }
        if (less < r && r <= less + eq) { sT = ke; sRR = r - less; }
    }
    __syncthreads();
    unsigned T = sT;
    unsigned rr = sRR;

    unsigned lessC = 0, eqC = 0;
    #pragma unroll
    for (int i = 0; i < 8; i++) {
        lessC += (key[i] < T);
        eqC   += (key[i] == T);
    }
    unsigned packed = lessC | (eqC << 16);
    unsigned incl = blockScanIncl(packed, warpSums, t);
    unsigned lb = (incl & 0xFFFFu) - lessC;
    unsigned eb = (incl >> 16)     - eqC;

    int* oidx = g_idx + (size_t)p * KEEP;
    #pragma unroll
    for (int i = 0; i < 8; i++) {
        int j = t*8 + i;
        unsigned k = key[i];
        if (k < T) {
            oidx[lb + min(eb, rr)] = j;
            lb++;
        } else if (k == T) {
            if (eb < rr) oidx[lb + eb] = j;
            eb++;
        }
    }
}

// ---------------------------------------------------------------------------
// Attention: q/k/v fp16; warp-per-row AV.
// ---------------------------------------------------------------------------
#define PADR 68
__global__ __launch_bounds__(256) void attn_kernel(
    const float* __restrict__ pos_bias,
    const unsigned char* __restrict__ mask)
{
    __shared__ int   sidx[KEEP];
    __shared__ float qs[Wp][PADR];
    __shared__ float sd[Wp][PADR];
    __shared__ float pb_s[Wp][PADR];
    __shared__ unsigned char km_s[KEEP];
    __shared__ float partial[8][Wp][Dp];

    int p  = blockIdx.x;
    int nw = p & (NWp-1);
    int bh = p >> 9;
    int h  = bh & (Hp-1);
    int b  = bh >> 3;
    int t  = threadIdx.x;

    if (t < KEEP) sidx[t] = g_idx[(size_t)p * KEEP + t];
    {
        int w = t >> 6, d = t & 63;
        qs[w][d] = __half2float(
            g_q16[((size_t)(b*Np + nw*Wp + w)*Hp + h)*Dp + d]);
    }
    __syncthreads();

    {
        int w = t >> 6, z = t & 63;
        int key = sidx[z];
        pb_s[w][z] = __ldg(pos_bias + ((size_t)h*Np + nw*Wp + w)*Np + key);
        if (t < KEEP) km_s[t] = mask[(size_t)b*Np + sidx[t]];
    }
    __syncthreads();

    const float scale = 0.125f;
    {
        int z = t >> 2, quar = t & 3;
        int row = sidx[z];
        const __half* kp = g_k16 + ((size_t)(b*Np + row)*Hp + h)*Dp + quar*16;
        uint4 kraw0 = __ldg((const uint4*)kp);
        uint4 kraw1 = __ldg((const uint4*)(kp + 8));
        __half2 kh[8];
        kh[0] = *(__half2*)&kraw0.x; kh[1] = *(__half2*)&kraw0.y;
        kh[2] = *(__half2*)&kraw0.z; kh[3] = *(__half2*)&kraw0.w;
        kh[4] = *(__half2*)&kraw1.x; kh[5] = *(__half2*)&kraw1.y;
        kh[6] = *(__half2*)&kraw1.z; kh[7] = *(__half2*)&kraw1.w;

        bool qm = mask[(size_t)b*Np + nw*Wp + quar] != 0;

        float pw[4] = {0.f, 0.f, 0.f, 0.f};
        #pragma unroll
        for (int i = 0; i < 8; i++) {
            float2 kf = __half22float2(kh[i]);
            #pragma unroll
            for (int w = 0; w < 4; w++) {
                float q0 = qs[w][quar*16 + i*2];
                float q1 = qs[w][quar*16 + i*2 + 1];
                pw[w] += q0*kf.x + q1*kf.y;
            }
        }
        #pragma unroll
        for (int w = 0; w < 4; w++) {
            pw[w] += __shfl_xor_sync(0xffffffffu, pw[w], 1);
            pw[w] += __shfl_xor_sync(0xffffffffu, pw[w], 2);
        }
        float val = pw[quar]*scale + pb_s[quar][z];
        if (qm && km_s[z]) val = -3.402823466e38f;
        sd[quar][z] = val;
    }
    __syncthreads();

    if (t < 128) {
        int w = t >> 5, lane = t & 31;
        float v0 = sd[w][lane], v1 = sd[w][lane+32];
        float m = fmaxf(v0, v1);
        #pragma unroll
        for (int off = 16; off > 0; off >>= 1)
            m = fmaxf(m, __shfl_xor_sync(0xffffffffu, m, off));
        float e0 = __expf(v0 - m), e1 = __expf(v1 - m);
        float s = e0 + e1;
        #pragma unroll
        for (int off = 16; off > 0; off >>= 1)
            s += __shfl_xor_sync(0xffffffffu, s, off);
        float inv = 1.f / s;
        sd[w][lane]    = e0*inv;
        sd[w][lane+32] = e1*inv;
    }
    __syncthreads();

    {
        int g = t >> 5, lane = t & 31;
        const __half* vbase = g_v16 + ((size_t)b*Np*Hp + h)*Dp + 2*lane;
        float sdv[4][8];
        #pragma unroll
        for (int w = 0; w < 4; w++) {
            float4 lo = *(const float4*)&sd[w][g*8];
            float4 hi = *(const float4*)&sd[w][g*8 + 4];
            sdv[w][0]=lo.x; sdv[w][1]=lo.y; sdv[w][2]=lo.z; sdv[w][3]=lo.w;
            sdv[w][4]=hi.x; sdv[w][5]=hi.y; sdv[w][6]=hi.z; sdv[w][7]=hi.w;
        }
        float a0[4], a1[4];
        #pragma unroll
        for (int w = 0; w < 4; w++) { a0[w] = 0.f; a1[w] = 0.f; }
        #pragma unroll
        for (int zi = 0; zi < 8; zi++) {
            int row = sidx[g*8 + zi];
            __half2 vv = __ldg((const __half2*)(vbase + (size_t)row*Hp*Dp));
            float2 vf = __half22float2(vv);
            #pragma unroll
            for (int w = 0; w < 4; w++) {
                a0[w] += sdv[w][zi] * vf.x;
                a1[w] += sdv[w][zi] * vf.y;
            }
        }
        #pragma unroll
        for (int w = 0; w < 4; w++)
            *(float2*)&partial[g][w][2*lane] = make_float2(a0[w], a1[w]);
    }
    __syncthreads();

    {
        int w = t >> 6, d = t & 63;
        float acc = 0.f;
        #pragma unroll
        for (int g = 0; g < 8; g++) acc += partial[g][w][d];
        g_attn16[((size_t)b*Np + nw*Wp + w)*(Hp*Dp) + h*Dp + d] = __float2half(acc);
    }
}

// ---------------------------------------------------------------------------
extern "C" void kernel_launch(void* const* d_in, const int* in_sizes, int n_in,
                              void* d_out, int out_size)
{
    const float* x            = (const float*)d_in[0];
    const unsigned char* mask = (const unsigned char*)d_in[1];
    const float* pos_bias     = (const float*)d_in[2];
    const float* pareto       = (const float*)d_in[3];
    const float* Wqkv         = (const float*)d_in[4];
    const float* bqkv         = (const float*)d_in[5];
    const float* Wo           = (const float*)d_in[6];
    const float* bo           = (const float*)d_in[7];
    float* out                = (float*)d_out;

    (void)in_sizes; (void)n_in; (void)out_size;

    static cudaStream_t s2 = nullptr;
    static cudaEvent_t evFork = nullptr, evPerm = nullptr, evJoin = nullptr, evWo = nullptr;
    if (s2 == nullptr) {
        cudaStreamCreateWithFlags(&s2, cudaStreamNonBlocking);
        cudaEventCreateWithFlags(&evFork, cudaEventDisableTiming);
        cudaEventCreateWithFlags(&evPerm, cudaEventDisableTiming);
        cudaEventCreateWithFlags(&evJoin, cudaEventDisableTiming);
        cudaEventCreateWithFlags(&evWo, cudaEventDisableTiming);
        cudaFuncSetAttribute(gemm_f16_kernel<0>,
            cudaFuncAttributeMaxDynamicSharedMemorySize, GEMM_SMEM);
        cudaFuncSetAttribute(gemm_f16_kernel<1>,
            cudaFuncAttributeMaxDynamicSharedMemorySize, GEMM_SMEM);
    }

    // Side stream: producers for gemm0, select (evJoin), then Wo transpose.
    cudaEventRecord(evFork, 0);
    cudaStreamWaitEvent(s2, evFork, 0);
    permW_kernel<<<dim3(48,16), dim3(32,32), 0, s2>>>(Wqkv, bqkv);
    convX_kernel<<<(Bp*Np*Cp/4)/256, 256, 0, s2>>>(x);
    cudaEventRecord(evPerm, s2);
    select_kernel<<<Bp*Hp*NWp, 256, 0, s2>>>(pareto, mask);
    cudaEventRecord(evJoin, s2);
    convWo_kernel<<<dim3(16,16), dim3(32,32), 0, s2>>>(Wo);
    cudaEventRecord(evWo, s2);

    // QKV GEMM (fp16 tensor cores + ldmatrix).
    cudaStreamWaitEvent(0, evPerm, 0);
    {
        dim3 grid(3*Hp*Dp/128, Bp*Np/128);   // 12 x 64
        gemm_f16_kernel<0><<<grid, 256, GEMM_SMEM>>>(nullptr, nullptr, 3*Hp*Dp);
    }

    // Attention (needs q/k/v + g_idx).
    cudaStreamWaitEvent(0, evJoin, 0);
    attn_kernel<<<Bp*Hp*NWp, 256>>>(pos_bias, mask);

    // Output projection (needs g_attn16 + g_Wo16).
    cudaStreamWaitEvent(0, evWo, 0);
    {
        dim3 grid(Cp/128, Bp*Np/128);        // 4 x 64
        gemm_f16_kernel<1><<<grid, 256, GEMM_SMEM>>>(bo, out, Cp);
    }
}